// round 6
// baseline (speedup 1.0000x reference)
#include <cuda_runtime.h>
#include <cuda_bf16.h>
#include <math.h>
#include <stdint.h>

#define BATCH 4
#define SEQ   8192
#define CH    768
#define N2    4096
#define MODES 4097
#define NBLK  8
#define LAM   0.01f

#define FWD_SCALE 0.011048543456039806f   // 1/sqrt(8192)
#define INV_SCALE 0.022097086912079613f   // sqrt(8192)/4096

// padded smem indexing: 1 extra float2 per 32 -> kills 128B-stride conflicts
#define IX(i) ((i) + ((i) >> 5))
#define FFT_BUF 4224                      // IX(4095)=4222 < 4224
#define FFT_SMEM (2 * FFT_BUF * 8)        // 67584 bytes

// ---------------- device scratch ----------------
__device__ float  g_Xre[BATCH * CH * MODES];
__device__ float  g_Xim[BATCH * CH * MODES];
__device__ float  g_yT [BATCH * CH * SEQ];
__device__ float2 g_wfft[N2];     // exp(-2*pi*i*t/4096)
__device__ float2 g_wr  [MODES];  // (cos,sin)(2*pi*k/8192)

// ---------------- tables ----------------
__global__ void init_tables_kernel() {
    int i = blockIdx.x * blockDim.x + threadIdx.x;
    if (i < N2) {
        float s, c;
        sincospif((float)i * (1.0f / 2048.0f), &s, &c);
        g_wfft[i] = make_float2(c, -s);
    }
    if (i < MODES) {
        float s, c;
        sincospif((float)i * (1.0f / 4096.0f), &s, &c);
        g_wr[i] = make_float2(c, s);
    }
}

// ---------------- complex helpers ----------------
__device__ __forceinline__ float2 cadd(float2 a, float2 b) { return make_float2(a.x + b.x, a.y + b.y); }
__device__ __forceinline__ float2 csub(float2 a, float2 b) { return make_float2(a.x - b.x, a.y - b.y); }
__device__ __forceinline__ float2 cmul(float2 a, float2 b) {
    return make_float2(fmaf(a.x, b.x, -a.y * b.y), fmaf(a.x, b.y, a.y * b.x));
}

// forward DFT4 (e^{-i}), in place
__device__ __forceinline__ void dft4(float2& a0, float2& a1, float2& a2, float2& a3) {
    float2 t0 = cadd(a0, a2), t1 = csub(a0, a2);
    float2 t2 = cadd(a1, a3), t3 = csub(a1, a3);
    a0 = cadd(t0, t2);
    a2 = csub(t0, t2);
    a1 = make_float2(t1.x + t3.y, t1.y - t3.x);   // t1 - i t3
    a3 = make_float2(t1.x - t3.y, t1.y + t3.x);   // t1 + i t3
}

// 16-pt DFT in registers; output X[j] lands in v[4*(j&3) + (j>>2)]
__device__ __forceinline__ void dft16(float2 v[16]) {
    #pragma unroll
    for (int i = 0; i < 4; i++) dft4(v[i], v[i + 4], v[i + 8], v[i + 12]);
    const float C1 = 0.92387953251128674f, S1 = 0.38268343236508978f, R = 0.70710678118654752f;
    v[5]  = cmul(make_float2( C1, -S1), v[5]);
    v[6]  = cmul(make_float2(  R,  -R), v[6]);
    v[7]  = cmul(make_float2( S1, -C1), v[7]);
    v[9]  = cmul(make_float2(  R,  -R), v[9]);
    v[10] = make_float2(v[10].y, -v[10].x);        // * -i
    v[11] = cmul(make_float2( -R,  -R), v[11]);
    v[13] = cmul(make_float2( S1, -C1), v[13]);
    v[14] = cmul(make_float2( -R,  -R), v[14]);
    v[15] = cmul(make_float2(-C1,  S1), v[15]);
    #pragma unroll
    for (int k1 = 0; k1 < 4; k1++) dft4(v[4 * k1], v[4 * k1 + 1], v[4 * k1 + 2], v[4 * k1 + 3]);
}

// ---------------- 4096-pt radix-16 Stockham (forward, e^{-i}), 3 stages -----
__device__ float2* fft4096_r16(float2* A, float2* B) {
    float2* src = A;
    float2* dst = B;
    int ls = 0;
    #pragma unroll
    for (int stage = 0; stage < 3; stage++) {
        int m = 256 >> (4 * stage);
        int idx = threadIdx.x;
        int q = idx & ((1 << ls) - 1);
        int p = idx >> ls;
        float2 v[16];
        #pragma unroll
        for (int j = 0; j < 16; j++)
            v[j] = src[IX(q + ((p + j * m) << ls))];
        dft16(v);
        int twb = p << ls;   // stage 2 has p==0 -> all twiddles = 1
        #pragma unroll
        for (int j = 0; j < 16; j++) {
            float2 y = v[4 * (j & 3) + (j >> 2)];
            float2 w = g_wfft[j * twb];
            dst[IX(q + ((16 * p + j) << ls))] = cmul(w, y);
        }
        __syncthreads();
        float2* t = src; src = dst; dst = t;
        ls += 4;
    }
    return src;
}

// ---------------- forward rfft: x[b,s,c] -> X planar [b*CH+c][k] ------------
__global__ void __launch_bounds__(256, 3) fwd_fft_kernel(const float* __restrict__ x) {
    extern __shared__ char smraw[];
    float2* A = (float2*)smraw;
    float2* B = A + FFT_BUF;
    int row = blockIdx.x;
    int b = row / CH, c = row % CH;
    const float* xr = x + ((size_t)b * SEQ) * CH + c;
    for (int j = threadIdx.x; j < 4096; j += 256) {
        A[IX(j)] = make_float2(xr[(size_t)(2 * j) * CH], xr[(size_t)(2 * j + 1) * CH]);
    }
    __syncthreads();
    float2* R = fft4096_r16(A, B);
    float* Xre = g_Xre + (size_t)row * MODES;
    float* Xim = g_Xim + (size_t)row * MODES;
    for (int k = threadIdx.x; k <= 4096; k += 256) {
        float2 Zk = R[IX(k & 4095)];
        float2 Zc = R[IX((4096 - k) & 4095)];
        float Ex = 0.5f * (Zk.x + Zc.x), Ey = 0.5f * (Zk.y - Zc.y);
        float Ox = 0.5f * (Zk.x - Zc.x), Oy = 0.5f * (Zk.y + Zc.y);
        float2 w = g_wr[k];
        float re = Ex + w.x * Oy - w.y * Ox;
        float im = Ey - w.x * Ox - w.y * Oy;
        Xre[k] = FWD_SCALE * re;
        Xim[k] = FWD_SCALE * im;
    }
}

// ============== tensor-core block-diagonal complex 2-layer MLP ==============
// CTA = (mode-tile of 256, block n, batch b). 8 warps x 32 modes (2 passes of 16).
// 4 weight planes (w1r,w1i,w2r,w2i); -wi products done by sign-flipping the
// bf16x2 A-fragment in registers (exact).
#define MT    256
#define XPAD  98
#define SW_OFF   0                           // 4 * 96 * 98 bf16 = 75264
#define SXR_OFF  (4 * 96 * XPAD * 2)
#define SXI_OFF  (SXR_OFF + MT * XPAD * 2)   // +50176
#define SB_OFF   (SXI_OFF + MT * XPAD * 2)   // +50176
#define MLP_SMEM (SB_OFF + 4 * 96 * 4)       // +1536 = 177152

__device__ __forceinline__ void mma_bf16(float* c, const uint32_t* a, uint32_t b0, uint32_t b1) {
    asm volatile(
        "mma.sync.aligned.m16n8k16.row.col.f32.bf16.bf16.f32 "
        "{%0,%1,%2,%3}, {%4,%5,%6,%7}, {%8,%9}, {%0,%1,%2,%3};"
        : "+f"(c[0]), "+f"(c[1]), "+f"(c[2]), "+f"(c[3])
        : "r"(a[0]), "r"(a[1]), "r"(a[2]), "r"(a[3]), "r"(b0), "r"(b1));
}

__global__ void __launch_bounds__(256) mlp_mma_kernel(const float* __restrict__ w1,
                                                      const float* __restrict__ b1,
                                                      const float* __restrict__ w2,
                                                      const float* __restrict__ b2) {
    extern __shared__ char sm[];
    __nv_bfloat16* s_w  = (__nv_bfloat16*)(sm + SW_OFF);   // [4][96][XPAD]: w1r,w1i,w2r,w2i
    __nv_bfloat16* s_xr = (__nv_bfloat16*)(sm + SXR_OFF);  // [MT][XPAD]
    __nv_bfloat16* s_xi = (__nv_bfloat16*)(sm + SXI_OFF);
    float*         s_bv = (float*)(sm + SB_OFF);           // [4][96]

    const int tid = threadIdx.x;
    const int n   = blockIdx.y;
    const int b   = blockIdx.z;
    const int m0  = blockIdx.x * MT;

    const float* g_w1r = w1 + n * 9216;
    const float* g_w1i = w1 + 73728 + n * 9216;
    const float* g_w2r = w2 + n * 9216;
    const float* g_w2i = w2 + 73728 + n * 9216;
    for (int i = tid; i < 9216; i += 256) {
        int d = i / 96, k = i % 96;
        int o = k * XPAD + d;
        s_w[0 * 96 * XPAD + o] = __float2bfloat16_rn(g_w1r[i]);
        s_w[1 * 96 * XPAD + o] = __float2bfloat16_rn(g_w1i[i]);
        s_w[2 * 96 * XPAD + o] = __float2bfloat16_rn(g_w2r[i]);
        s_w[3 * 96 * XPAD + o] = __float2bfloat16_rn(g_w2i[i]);
    }
    if (tid < 96) {
        s_bv[tid]       = b1[n * 96 + tid];
        s_bv[96 + tid]  = b1[768 + n * 96 + tid];
        s_bv[192 + tid] = b2[n * 96 + tid];
        s_bv[288 + tid] = b2[768 + n * 96 + tid];
    }

    size_t rowbase = ((size_t)b * CH + n * 96) * (size_t)MODES;
    for (int i = tid; i < 96 * MT; i += 256) {
        int d = i >> 8, mm = i & (MT - 1);
        int mode = m0 + mm;
        bool ok = mode < MODES;
        float vr = ok ? g_Xre[rowbase + (size_t)d * MODES + mode] : 0.0f;
        float vi = ok ? g_Xim[rowbase + (size_t)d * MODES + mode] : 0.0f;
        s_xr[mm * XPAD + d] = __float2bfloat16_rn(vr);
        s_xi[mm * XPAD + d] = __float2bfloat16_rn(vi);
    }
    __syncthreads();

    const int lane = tid & 31;
    const int warp = tid >> 5;
    const int g  = lane >> 2;
    const int t  = lane & 3;

    const uint32_t* Ww = (const uint32_t*)s_w;
    const uint32_t* Xr = (const uint32_t*)s_xr;
    const uint32_t* Xi = (const uint32_t*)s_xi;
    const int RS = XPAD / 2;   // 49
    const uint32_t SGN = 0x80008000u;

    for (int h = 0; h < 2; h++) {
        const int mrow = warp * 32 + h * 16;
        float cr[12][4], ci[12][4];

        // ---------- layer 1: o_r = xr*wr + (-xi)*wi ; o_i = xi*wr + xr*wi ----------
        #pragma unroll
        for (int nt = 0; nt < 12; nt++) {
            float br0 = s_bv[nt * 8 + 2 * t], br1 = s_bv[nt * 8 + 2 * t + 1];
            float bi0 = s_bv[96 + nt * 8 + 2 * t], bi1 = s_bv[96 + nt * 8 + 2 * t + 1];
            cr[nt][0] = br0; cr[nt][1] = br1; cr[nt][2] = br0; cr[nt][3] = br1;
            ci[nt][0] = bi0; ci[nt][1] = bi1; ci[nt][2] = bi0; ci[nt][3] = bi1;
        }
        #pragma unroll
        for (int k = 0; k < 6; k++) {
            int kw = k * 8 + t;
            uint32_t ar[4], ai[4], nai[4];
            ar[0] = Xr[(mrow + g) * RS + kw];     ar[1] = Xr[(mrow + g + 8) * RS + kw];
            ar[2] = Xr[(mrow + g) * RS + kw + 4]; ar[3] = Xr[(mrow + g + 8) * RS + kw + 4];
            ai[0] = Xi[(mrow + g) * RS + kw];     ai[1] = Xi[(mrow + g + 8) * RS + kw];
            ai[2] = Xi[(mrow + g) * RS + kw + 4]; ai[3] = Xi[(mrow + g + 8) * RS + kw + 4];
            #pragma unroll
            for (int j = 0; j < 4; j++) nai[j] = ai[j] ^ SGN;
            #pragma unroll
            for (int nt = 0; nt < 12; nt++) {
                int wrow = (nt * 8 + g) * RS + kw;
                uint32_t wr0 = Ww[0 * 96 * RS + wrow], wr1 = Ww[0 * 96 * RS + wrow + 4];
                uint32_t wi0 = Ww[1 * 96 * RS + wrow], wi1 = Ww[1 * 96 * RS + wrow + 4];
                mma_bf16(cr[nt], ar,  wr0, wr1);
                mma_bf16(cr[nt], nai, wi0, wi1);
                mma_bf16(ci[nt], ai,  wr0, wr1);
                mma_bf16(ci[nt], ar,  wi0, wi1);
            }
        }
        __syncwarp();
        {
            uint32_t* Xrw = (uint32_t*)s_xr;
            uint32_t* Xiw = (uint32_t*)s_xi;
            #pragma unroll
            for (int nt = 0; nt < 12; nt++) {
                int cw = nt * 4 + t;
                __nv_bfloat162 hh;
                hh = __floats2bfloat162_rn(fmaxf(cr[nt][0], 0.0f), fmaxf(cr[nt][1], 0.0f));
                Xrw[(mrow + g) * RS + cw] = *(uint32_t*)&hh;
                hh = __floats2bfloat162_rn(fmaxf(cr[nt][2], 0.0f), fmaxf(cr[nt][3], 0.0f));
                Xrw[(mrow + g + 8) * RS + cw] = *(uint32_t*)&hh;
                hh = __floats2bfloat162_rn(fmaxf(ci[nt][0], 0.0f), fmaxf(ci[nt][1], 0.0f));
                Xiw[(mrow + g) * RS + cw] = *(uint32_t*)&hh;
                hh = __floats2bfloat162_rn(fmaxf(ci[nt][2], 0.0f), fmaxf(ci[nt][3], 0.0f));
                Xiw[(mrow + g + 8) * RS + cw] = *(uint32_t*)&hh;
            }
        }
        __syncwarp();

        // ---------- layer 2 ----------
        #pragma unroll
        for (int nt = 0; nt < 12; nt++) {
            float br0 = s_bv[192 + nt * 8 + 2 * t], br1 = s_bv[192 + nt * 8 + 2 * t + 1];
            float bi0 = s_bv[288 + nt * 8 + 2 * t], bi1 = s_bv[288 + nt * 8 + 2 * t + 1];
            cr[nt][0] = br0; cr[nt][1] = br1; cr[nt][2] = br0; cr[nt][3] = br1;
            ci[nt][0] = bi0; ci[nt][1] = bi1; ci[nt][2] = bi0; ci[nt][3] = bi1;
        }
        #pragma unroll
        for (int k = 0; k < 6; k++) {
            int kw = k * 8 + t;
            uint32_t ar[4], ai[4], nai[4];
            ar[0] = Xr[(mrow + g) * RS + kw];     ar[1] = Xr[(mrow + g + 8) * RS + kw];
            ar[2] = Xr[(mrow + g) * RS + kw + 4]; ar[3] = Xr[(mrow + g + 8) * RS + kw + 4];
            ai[0] = Xi[(mrow + g) * RS + kw];     ai[1] = Xi[(mrow + g + 8) * RS + kw];
            ai[2] = Xi[(mrow + g) * RS + kw + 4]; ai[3] = Xi[(mrow + g + 8) * RS + kw + 4];
            #pragma unroll
            for (int j = 0; j < 4; j++) nai[j] = ai[j] ^ SGN;
            #pragma unroll
            for (int nt = 0; nt < 12; nt++) {
                int wrow = (nt * 8 + g) * RS + kw;
                uint32_t wr0 = Ww[2 * 96 * RS + wrow], wr1 = Ww[2 * 96 * RS + wrow + 4];
                uint32_t wi0 = Ww[3 * 96 * RS + wrow], wi1 = Ww[3 * 96 * RS + wrow + 4];
                mma_bf16(cr[nt], ar,  wr0, wr1);
                mma_bf16(cr[nt], nai, wi0, wi1);
                mma_bf16(ci[nt], ai,  wr0, wr1);
                mma_bf16(ci[nt], ar,  wi0, wi1);
            }
        }

        // ---------- softshrink + store ----------
        int mode_lo = m0 + mrow + g;
        int mode_hi = mode_lo + 8;
        #pragma unroll
        for (int nt = 0; nt < 12; nt++) {
            #pragma unroll
            for (int j = 0; j < 4; j++) {
                int col  = nt * 8 + 2 * t + (j & 1);
                int mode = (j < 2) ? mode_lo : mode_hi;
                if (mode < MODES) {
                    size_t off = rowbase + (size_t)col * MODES + mode;
                    float vr = cr[nt][j];
                    float vi = ci[nt][j];
                    g_Xre[off] = copysignf(fmaxf(fabsf(vr) - LAM, 0.0f), vr);
                    g_Xim[off] = copysignf(fmaxf(fabsf(vi) - LAM, 0.0f), vi);
                }
            }
        }
    }
}

// ---------------- inverse rfft: X planar -> yT[b*CH+c][s] -------------------
__global__ void __launch_bounds__(256, 3) inv_fft_kernel() {
    extern __shared__ char smraw[];
    float2* A = (float2*)smraw;
    float2* B = A + FFT_BUF;
    int row = blockIdx.x;
    const float* Xre = g_Xre + (size_t)row * MODES;
    const float* Xim = g_Xim + (size_t)row * MODES;
    for (int k = threadIdx.x; k < 4096; k += 256) {
        float xkr = Xre[k],        xki = Xim[k];
        float xcr = Xre[4096 - k], xci = Xim[4096 - k];
        if (k == 0) { xki = 0.0f; xci = 0.0f; }
        float Ex = 0.5f * (xkr + xcr), Ey = 0.5f * (xki - xci);
        float Gx = 0.5f * (xkr - xcr), Gy = 0.5f * (xki + xci);
        float2 w = g_wr[k];
        float WOx = w.x * Gx - w.y * Gy;
        float WOy = w.x * Gy + w.y * Gx;
        float Zx = Ex - WOy;
        float Zy = Ey + WOx;
        A[IX(k)] = make_float2(INV_SCALE * Zx, -INV_SCALE * Zy);
    }
    __syncthreads();
    float2* R = fft4096_r16(A, B);
    float2* out = (float2*)(g_yT + (size_t)row * SEQ);
    for (int j = threadIdx.x; j < 4096; j += 256) {
        float2 r = R[IX(j)];
        out[j] = make_float2(r.x, -r.y);
    }
}

// ---------------- transpose + bias: out[b,s,c] = x[b,s,c] + yT[b,c,s] -------
__global__ void __launch_bounds__(256) final_kernel(const float* __restrict__ x,
                                                    float* __restrict__ out) {
    __shared__ float t[32][33];
    int b  = blockIdx.z;
    int c0 = blockIdx.x * 32;
    int s0 = blockIdx.y * 32;
    int tx = threadIdx.x, ty = threadIdx.y;
    #pragma unroll
    for (int i = 0; i < 4; i++) {
        int cc = c0 + ty + 8 * i;
        t[ty + 8 * i][tx] = g_yT[((size_t)b * CH + cc) * SEQ + s0 + tx];
    }
    __syncthreads();
    #pragma unroll
    for (int i = 0; i < 4; i++) {
        int s = s0 + ty + 8 * i;
        size_t off = ((size_t)b * SEQ + s) * CH + c0 + tx;
        out[off] = x[off] + t[tx][ty + 8 * i];
    }
}

// ---------------- launcher ----------------
extern "C" void kernel_launch(void* const* d_in, const int* in_sizes, int n_in,
                              void* d_out, int out_size) {
    const float* x  = (const float*)d_in[0];
    const float* w1 = (const float*)d_in[1];
    const float* b1 = (const float*)d_in[2];
    const float* w2 = (const float*)d_in[3];
    const float* b2 = (const float*)d_in[4];
    float* out = (float*)d_out;

    cudaFuncSetAttribute(fwd_fft_kernel, cudaFuncAttributeMaxDynamicSharedMemorySize, FFT_SMEM);
    cudaFuncSetAttribute(inv_fft_kernel, cudaFuncAttributeMaxDynamicSharedMemorySize, FFT_SMEM);
    cudaFuncSetAttribute(mlp_mma_kernel, cudaFuncAttributeMaxDynamicSharedMemorySize, MLP_SMEM);

    init_tables_kernel<<<17, 256>>>();
    fwd_fft_kernel<<<BATCH * CH, 256, FFT_SMEM>>>(x);
    mlp_mma_kernel<<<dim3((MODES + MT - 1) / MT, NBLK, BATCH), 256, MLP_SMEM>>>(w1, b1, w2, b2);
    inv_fft_kernel<<<BATCH * CH, 256, FFT_SMEM>>>();
    final_kernel<<<dim3(CH / 32, SEQ / 32, BATCH), dim3(32, 8)>>>(x, out);
}

// round 7
// speedup vs baseline: 1.1953x; 1.1953x over previous
#include <cuda_runtime.h>
#include <cuda_bf16.h>
#include <math.h>
#include <stdint.h>

#define BATCH 4
#define SEQ   8192
#define CH    768
#define N2    4096
#define MODES 4097
#define NBLK  8
#define LAM   0.01f

#define FWD_SCALE 0.011048543456039806f   // 1/sqrt(8192)
#define INV_SCALE 0.022097086912079613f   // sqrt(8192)/4096

// padded smem indexing: 1 extra float2 per 32 -> kills 128B-stride conflicts
#define IX(i) ((i) + ((i) >> 5))
#define FFT_BUF 4224
#define FFT_SMEM (2 * FFT_BUF * 8)        // 67584 bytes

// ---------------- device scratch (bf16 intermediates) ----------------
__device__ __nv_bfloat16 g_Xre[BATCH * CH * MODES];
__device__ __nv_bfloat16 g_Xim[BATCH * CH * MODES];
__device__ __nv_bfloat16 g_yT [BATCH * CH * SEQ];
__device__ float2 g_wfft[N2];     // exp(-2*pi*i*t/4096)
__device__ float2 g_wr  [MODES];  // (cos,sin)(2*pi*k/8192)

// ---------------- tables ----------------
__global__ void init_tables_kernel() {
    int i = blockIdx.x * blockDim.x + threadIdx.x;
    if (i < N2) {
        float s, c;
        sincospif((float)i * (1.0f / 2048.0f), &s, &c);
        g_wfft[i] = make_float2(c, -s);
    }
    if (i < MODES) {
        float s, c;
        sincospif((float)i * (1.0f / 4096.0f), &s, &c);
        g_wr[i] = make_float2(c, s);
    }
}

// ---------------- complex helpers ----------------
__device__ __forceinline__ float2 cadd(float2 a, float2 b) { return make_float2(a.x + b.x, a.y + b.y); }
__device__ __forceinline__ float2 csub(float2 a, float2 b) { return make_float2(a.x - b.x, a.y - b.y); }
__device__ __forceinline__ float2 cmul(float2 a, float2 b) {
    return make_float2(fmaf(a.x, b.x, -a.y * b.y), fmaf(a.x, b.y, a.y * b.x));
}

// forward DFT4 (e^{-i}), in place
__device__ __forceinline__ void dft4(float2& a0, float2& a1, float2& a2, float2& a3) {
    float2 t0 = cadd(a0, a2), t1 = csub(a0, a2);
    float2 t2 = cadd(a1, a3), t3 = csub(a1, a3);
    a0 = cadd(t0, t2);
    a2 = csub(t0, t2);
    a1 = make_float2(t1.x + t3.y, t1.y - t3.x);
    a3 = make_float2(t1.x - t3.y, t1.y + t3.x);
}

// 16-pt DFT in registers; output X[j] lands in v[4*(j&3) + (j>>2)]
__device__ __forceinline__ void dft16(float2 v[16]) {
    #pragma unroll
    for (int i = 0; i < 4; i++) dft4(v[i], v[i + 4], v[i + 8], v[i + 12]);
    const float C1 = 0.92387953251128674f, S1 = 0.38268343236508978f, R = 0.70710678118654752f;
    v[5]  = cmul(make_float2( C1, -S1), v[5]);
    v[6]  = cmul(make_float2(  R,  -R), v[6]);
    v[7]  = cmul(make_float2( S1, -C1), v[7]);
    v[9]  = cmul(make_float2(  R,  -R), v[9]);
    v[10] = make_float2(v[10].y, -v[10].x);
    v[11] = cmul(make_float2( -R,  -R), v[11]);
    v[13] = cmul(make_float2( S1, -C1), v[13]);
    v[14] = cmul(make_float2( -R,  -R), v[14]);
    v[15] = cmul(make_float2(-C1,  S1), v[15]);
    #pragma unroll
    for (int k1 = 0; k1 < 4; k1++) dft4(v[4 * k1], v[4 * k1 + 1], v[4 * k1 + 2], v[4 * k1 + 3]);
}

// ---------------- 4096-pt radix-16 Stockham (forward, e^{-i}), 3 stages -----
__device__ float2* fft4096_r16(float2* A, float2* B) {
    float2* src = A;
    float2* dst = B;
    int ls = 0;
    #pragma unroll
    for (int stage = 0; stage < 3; stage++) {
        int m = 256 >> (4 * stage);
        int idx = threadIdx.x;
        int q = idx & ((1 << ls) - 1);
        int p = idx >> ls;
        float2 v[16];
        #pragma unroll
        for (int j = 0; j < 16; j++)
            v[j] = src[IX(q + ((p + j * m) << ls))];
        dft16(v);
        int twb = p << ls;
        #pragma unroll
        for (int j = 0; j < 16; j++) {
            float2 y = v[4 * (j & 3) + (j >> 2)];
            float2 w = g_wfft[j * twb];
            dst[IX(q + ((16 * p + j) << ls))] = cmul(w, y);
        }
        __syncthreads();
        float2* t = src; src = dst; dst = t;
        ls += 4;
    }
    return src;
}

// ---------------- forward rfft: x[b,s,c] -> X planar bf16 [b*CH+c][k] -------
__global__ void __launch_bounds__(256, 2) fwd_fft_kernel(const float* __restrict__ x) {
    extern __shared__ char smraw[];
    float2* A = (float2*)smraw;
    float2* B = A + FFT_BUF;
    int row = blockIdx.x;
    int b = row / CH, c = row % CH;
    const float* xr = x + ((size_t)b * SEQ) * CH + c;
    for (int j = threadIdx.x; j < 4096; j += 256) {
        A[IX(j)] = make_float2(xr[(size_t)(2 * j) * CH], xr[(size_t)(2 * j + 1) * CH]);
    }
    __syncthreads();
    float2* R = fft4096_r16(A, B);
    __nv_bfloat16* Xre = g_Xre + (size_t)row * MODES;
    __nv_bfloat16* Xim = g_Xim + (size_t)row * MODES;
    for (int k = threadIdx.x; k <= 4096; k += 256) {
        float2 Zk = R[IX(k & 4095)];
        float2 Zc = R[IX((4096 - k) & 4095)];
        float Ex = 0.5f * (Zk.x + Zc.x), Ey = 0.5f * (Zk.y - Zc.y);
        float Ox = 0.5f * (Zk.x - Zc.x), Oy = 0.5f * (Zk.y + Zc.y);
        float2 w = g_wr[k];
        float re = Ex + w.x * Oy - w.y * Ox;
        float im = Ey - w.x * Ox - w.y * Oy;
        Xre[k] = __float2bfloat16_rn(FWD_SCALE * re);
        Xim[k] = __float2bfloat16_rn(FWD_SCALE * im);
    }
}

// ============== tensor-core block-diagonal complex 2-layer MLP ==============
// (R5 structure: 6 weight planes incl. pre-negated -wi; bf16 gmem spectrum)
#define MT    256
#define XPAD  98
#define SW_OFF   0                           // 6 * 96 * 98 bf16 = 112896
#define SXR_OFF  (6 * 96 * XPAD * 2)
#define SXI_OFF  (SXR_OFF + MT * XPAD * 2)   // +50176
#define SB_OFF   (SXI_OFF + MT * XPAD * 2)   // +50176
#define MLP_SMEM (SB_OFF + 4 * 96 * 4)       // +1536 = 214784

__device__ __forceinline__ void mma_bf16(float* c, const uint32_t* a, uint32_t b0, uint32_t b1) {
    asm volatile(
        "mma.sync.aligned.m16n8k16.row.col.f32.bf16.bf16.f32 "
        "{%0,%1,%2,%3}, {%4,%5,%6,%7}, {%8,%9}, {%0,%1,%2,%3};"
        : "+f"(c[0]), "+f"(c[1]), "+f"(c[2]), "+f"(c[3])
        : "r"(a[0]), "r"(a[1]), "r"(a[2]), "r"(a[3]), "r"(b0), "r"(b1));
}

__global__ void __launch_bounds__(256) mlp_mma_kernel(const float* __restrict__ w1,
                                                      const float* __restrict__ b1,
                                                      const float* __restrict__ w2,
                                                      const float* __restrict__ b2) {
    extern __shared__ char sm[];
    __nv_bfloat16* s_w  = (__nv_bfloat16*)(sm + SW_OFF);   // [6][96][XPAD]: w1r,w1i,-w1i,w2r,w2i,-w2i
    __nv_bfloat16* s_xr = (__nv_bfloat16*)(sm + SXR_OFF);  // [MT][XPAD]
    __nv_bfloat16* s_xi = (__nv_bfloat16*)(sm + SXI_OFF);
    float*         s_bv = (float*)(sm + SB_OFF);           // [4][96]

    const int tid = threadIdx.x;
    const int n   = blockIdx.y;
    const int b   = blockIdx.z;
    const int m0  = blockIdx.x * MT;

    const float* g_w1r = w1 + n * 9216;
    const float* g_w1i = w1 + 73728 + n * 9216;
    const float* g_w2r = w2 + n * 9216;
    const float* g_w2i = w2 + 73728 + n * 9216;
    for (int i = tid; i < 9216; i += 256) {
        int d = i / 96, k = i % 96;
        int o = k * XPAD + d;
        float v;
        v = g_w1r[i]; s_w[0 * 96 * XPAD + o] = __float2bfloat16_rn(v);
        v = g_w1i[i]; s_w[1 * 96 * XPAD + o] = __float2bfloat16_rn(v);
                      s_w[2 * 96 * XPAD + o] = __float2bfloat16_rn(-v);
        v = g_w2r[i]; s_w[3 * 96 * XPAD + o] = __float2bfloat16_rn(v);
        v = g_w2i[i]; s_w[4 * 96 * XPAD + o] = __float2bfloat16_rn(v);
                      s_w[5 * 96 * XPAD + o] = __float2bfloat16_rn(-v);
    }
    if (tid < 96) {
        s_bv[tid]       = b1[n * 96 + tid];
        s_bv[96 + tid]  = b1[768 + n * 96 + tid];
        s_bv[192 + tid] = b2[n * 96 + tid];
        s_bv[288 + tid] = b2[768 + n * 96 + tid];
    }

    size_t rowbase = ((size_t)b * CH + n * 96) * (size_t)MODES;
    const __nv_bfloat16 BZ = __float2bfloat16_rn(0.0f);
    for (int i = tid; i < 96 * MT; i += 256) {
        int d = i >> 8, mm = i & (MT - 1);
        int mode = m0 + mm;
        bool ok = mode < MODES;
        s_xr[mm * XPAD + d] = ok ? g_Xre[rowbase + (size_t)d * MODES + mode] : BZ;
        s_xi[mm * XPAD + d] = ok ? g_Xim[rowbase + (size_t)d * MODES + mode] : BZ;
    }
    __syncthreads();

    const int lane = tid & 31;
    const int warp = tid >> 5;
    const int g  = lane >> 2;
    const int t  = lane & 3;

    const uint32_t* Ww = (const uint32_t*)s_w;
    const uint32_t* Xr = (const uint32_t*)s_xr;
    const uint32_t* Xi = (const uint32_t*)s_xi;
    const int RS = XPAD / 2;   // 49

    for (int h = 0; h < 2; h++) {
        const int mrow = warp * 32 + h * 16;
        float cr[12][4], ci[12][4];

        // ---------- layer 1 ----------
        #pragma unroll
        for (int nt = 0; nt < 12; nt++) {
            float br0 = s_bv[nt * 8 + 2 * t], br1 = s_bv[nt * 8 + 2 * t + 1];
            float bi0 = s_bv[96 + nt * 8 + 2 * t], bi1 = s_bv[96 + nt * 8 + 2 * t + 1];
            cr[nt][0] = br0; cr[nt][1] = br1; cr[nt][2] = br0; cr[nt][3] = br1;
            ci[nt][0] = bi0; ci[nt][1] = bi1; ci[nt][2] = bi0; ci[nt][3] = bi1;
        }
        #pragma unroll
        for (int k = 0; k < 6; k++) {
            int kw = k * 8 + t;
            uint32_t ar[4], ai[4];
            ar[0] = Xr[(mrow + g) * RS + kw];     ar[1] = Xr[(mrow + g + 8) * RS + kw];
            ar[2] = Xr[(mrow + g) * RS + kw + 4]; ar[3] = Xr[(mrow + g + 8) * RS + kw + 4];
            ai[0] = Xi[(mrow + g) * RS + kw];     ai[1] = Xi[(mrow + g + 8) * RS + kw];
            ai[2] = Xi[(mrow + g) * RS + kw + 4]; ai[3] = Xi[(mrow + g + 8) * RS + kw + 4];
            #pragma unroll
            for (int nt = 0; nt < 12; nt++) {
                int wrow = (nt * 8 + g) * RS + kw;
                uint32_t wr0  = Ww[0 * 96 * RS + wrow], wr1  = Ww[0 * 96 * RS + wrow + 4];
                uint32_t wi0  = Ww[1 * 96 * RS + wrow], wi1  = Ww[1 * 96 * RS + wrow + 4];
                uint32_t nwi0 = Ww[2 * 96 * RS + wrow], nwi1 = Ww[2 * 96 * RS + wrow + 4];
                mma_bf16(cr[nt], ar, wr0, wr1);
                mma_bf16(cr[nt], ai, nwi0, nwi1);
                mma_bf16(ci[nt], ai, wr0, wr1);
                mma_bf16(ci[nt], ar, wi0, wi1);
            }
        }
        __syncwarp();
        {
            uint32_t* Xrw = (uint32_t*)s_xr;
            uint32_t* Xiw = (uint32_t*)s_xi;
            #pragma unroll
            for (int nt = 0; nt < 12; nt++) {
                int cw = nt * 4 + t;
                __nv_bfloat162 hh;
                hh = __floats2bfloat162_rn(fmaxf(cr[nt][0], 0.0f), fmaxf(cr[nt][1], 0.0f));
                Xrw[(mrow + g) * RS + cw] = *(uint32_t*)&hh;
                hh = __floats2bfloat162_rn(fmaxf(cr[nt][2], 0.0f), fmaxf(cr[nt][3], 0.0f));
                Xrw[(mrow + g + 8) * RS + cw] = *(uint32_t*)&hh;
                hh = __floats2bfloat162_rn(fmaxf(ci[nt][0], 0.0f), fmaxf(ci[nt][1], 0.0f));
                Xiw[(mrow + g) * RS + cw] = *(uint32_t*)&hh;
                hh = __floats2bfloat162_rn(fmaxf(ci[nt][2], 0.0f), fmaxf(ci[nt][3], 0.0f));
                Xiw[(mrow + g + 8) * RS + cw] = *(uint32_t*)&hh;
            }
        }
        __syncwarp();

        // ---------- layer 2 ----------
        #pragma unroll
        for (int nt = 0; nt < 12; nt++) {
            float br0 = s_bv[192 + nt * 8 + 2 * t], br1 = s_bv[192 + nt * 8 + 2 * t + 1];
            float bi0 = s_bv[288 + nt * 8 + 2 * t], bi1 = s_bv[288 + nt * 8 + 2 * t + 1];
            cr[nt][0] = br0; cr[nt][1] = br1; cr[nt][2] = br0; cr[nt][3] = br1;
            ci[nt][0] = bi0; ci[nt][1] = bi1; ci[nt][2] = bi0; ci[nt][3] = bi1;
        }
        #pragma unroll
        for (int k = 0; k < 6; k++) {
            int kw = k * 8 + t;
            uint32_t ar[4], ai[4];
            ar[0] = Xr[(mrow + g) * RS + kw];     ar[1] = Xr[(mrow + g + 8) * RS + kw];
            ar[2] = Xr[(mrow + g) * RS + kw + 4]; ar[3] = Xr[(mrow + g + 8) * RS + kw + 4];
            ai[0] = Xi[(mrow + g) * RS + kw];     ai[1] = Xi[(mrow + g + 8) * RS + kw];
            ai[2] = Xi[(mrow + g) * RS + kw + 4]; ai[3] = Xi[(mrow + g + 8) * RS + kw + 4];
            #pragma unroll
            for (int nt = 0; nt < 12; nt++) {
                int wrow = (nt * 8 + g) * RS + kw;
                uint32_t wr0  = Ww[3 * 96 * RS + wrow], wr1  = Ww[3 * 96 * RS + wrow + 4];
                uint32_t wi0  = Ww[4 * 96 * RS + wrow], wi1  = Ww[4 * 96 * RS + wrow + 4];
                uint32_t nwi0 = Ww[5 * 96 * RS + wrow], nwi1 = Ww[5 * 96 * RS + wrow + 4];
                mma_bf16(cr[nt], ar, wr0, wr1);
                mma_bf16(cr[nt], ai, nwi0, nwi1);
                mma_bf16(ci[nt], ai, wr0, wr1);
                mma_bf16(ci[nt], ar, wi0, wi1);
            }
        }

        // ---------- softshrink + store (bf16) ----------
        int mode_lo = m0 + mrow + g;
        int mode_hi = mode_lo + 8;
        #pragma unroll
        for (int nt = 0; nt < 12; nt++) {
            #pragma unroll
            for (int j = 0; j < 4; j++) {
                int col  = nt * 8 + 2 * t + (j & 1);
                int mode = (j < 2) ? mode_lo : mode_hi;
                if (mode < MODES) {
                    size_t off = rowbase + (size_t)col * MODES + mode;
                    float vr = cr[nt][j];
                    float vi = ci[nt][j];
                    g_Xre[off] = __float2bfloat16_rn(copysignf(fmaxf(fabsf(vr) - LAM, 0.0f), vr));
                    g_Xim[off] = __float2bfloat16_rn(copysignf(fmaxf(fabsf(vi) - LAM, 0.0f), vi));
                }
            }
        }
    }
}

// ---------------- inverse rfft: X planar bf16 -> yT bf16 [b*CH+c][s] --------
__global__ void __launch_bounds__(256, 3) inv_fft_kernel() {
    extern __shared__ char smraw[];
    float2* A = (float2*)smraw;
    float2* B = A + FFT_BUF;
    int row = blockIdx.x;
    const __nv_bfloat16* Xre = g_Xre + (size_t)row * MODES;
    const __nv_bfloat16* Xim = g_Xim + (size_t)row * MODES;
    for (int k = threadIdx.x; k < 4096; k += 256) {
        float xkr = __bfloat162float(Xre[k]);
        float xki = __bfloat162float(Xim[k]);
        float xcr = __bfloat162float(Xre[4096 - k]);
        float xci = __bfloat162float(Xim[4096 - k]);
        if (k == 0) { xki = 0.0f; xci = 0.0f; }
        float Ex = 0.5f * (xkr + xcr), Ey = 0.5f * (xki - xci);
        float Gx = 0.5f * (xkr - xcr), Gy = 0.5f * (xki + xci);
        float2 w = g_wr[k];
        float WOx = w.x * Gx - w.y * Gy;
        float WOy = w.x * Gy + w.y * Gx;
        float Zx = Ex - WOy;
        float Zy = Ey + WOx;
        A[IX(k)] = make_float2(INV_SCALE * Zx, -INV_SCALE * Zy);
    }
    __syncthreads();
    float2* R = fft4096_r16(A, B);
    __nv_bfloat162* out = (__nv_bfloat162*)(g_yT + (size_t)row * SEQ);
    for (int j = threadIdx.x; j < 4096; j += 256) {
        float2 r = R[IX(j)];
        out[j] = __floats2bfloat162_rn(r.x, -r.y);
    }
}

// ---------------- transpose + bias: out[b,s,c] = x[b,s,c] + yT[b,c,s] -------
__global__ void __launch_bounds__(256) final_kernel(const float* __restrict__ x,
                                                    float* __restrict__ out) {
    __shared__ float t[32][33];
    int b  = blockIdx.z;
    int c0 = blockIdx.x * 32;
    int s0 = blockIdx.y * 32;
    int tx = threadIdx.x, ty = threadIdx.y;
    #pragma unroll
    for (int i = 0; i < 4; i++) {
        int cc = c0 + ty + 8 * i;
        t[ty + 8 * i][tx] = __bfloat162float(g_yT[((size_t)b * CH + cc) * SEQ + s0 + tx]);
    }
    __syncthreads();
    #pragma unroll
    for (int i = 0; i < 4; i++) {
        int s = s0 + ty + 8 * i;
        size_t off = ((size_t)b * SEQ + s) * CH + c0 + tx;
        out[off] = x[off] + t[tx][ty + 8 * i];
    }
}

// ---------------- launcher ----------------
extern "C" void kernel_launch(void* const* d_in, const int* in_sizes, int n_in,
                              void* d_out, int out_size) {
    const float* x  = (const float*)d_in[0];
    const float* w1 = (const float*)d_in[1];
    const float* b1 = (const float*)d_in[2];
    const float* w2 = (const float*)d_in[3];
    const float* b2 = (const float*)d_in[4];
    float* out = (float*)d_out;

    cudaFuncSetAttribute(fwd_fft_kernel, cudaFuncAttributeMaxDynamicSharedMemorySize, FFT_SMEM);
    cudaFuncSetAttribute(inv_fft_kernel, cudaFuncAttributeMaxDynamicSharedMemorySize, FFT_SMEM);
    cudaFuncSetAttribute(mlp_mma_kernel, cudaFuncAttributeMaxDynamicSharedMemorySize, MLP_SMEM);

    init_tables_kernel<<<17, 256>>>();
    fwd_fft_kernel<<<BATCH * CH, 256, FFT_SMEM>>>(x);
    mlp_mma_kernel<<<dim3((MODES + MT - 1) / MT, NBLK, BATCH), 256, MLP_SMEM>>>(w1, b1, w2, b2);
    inv_fft_kernel<<<BATCH * CH, 256, FFT_SMEM>>>();
    final_kernel<<<dim3(CH / 32, SEQ / 32, BATCH), dim3(32, 8)>>>(x, out);
}

// round 8
// speedup vs baseline: 1.4054x; 1.1758x over previous
#include <cuda_runtime.h>
#include <cuda_bf16.h>
#include <math.h>
#include <stdint.h>

#define BATCH 4
#define SEQ   8192
#define CH    768
#define N2    4096
#define MODES 4097
#define NBLK  8
#define LAM   0.01f

#define FWD_SCALE 0.011048543456039806f   // 1/sqrt(8192)
#define INV_SCALE 0.022097086912079613f   // sqrt(8192)/4096

// padded smem indexing: 1 extra float2 per 32 -> kills 128B-stride conflicts
#define IX(i) ((i) + ((i) >> 5))
#define FFT_BUF 4224
#define FFT_SMEM (2 * FFT_BUF * 8)        // 67584 bytes

// ---------------- device scratch ----------------
__device__ float          g_xT[BATCH * CH * SEQ];        // x transposed [b][c][s], fp32
__device__ __nv_bfloat162 g_X [BATCH * CH * MODES];      // spectrum (re,im) bf16x2
__device__ __nv_bfloat16  g_yT[BATCH * CH * SEQ];        // irfft out [b][c][s]
__device__ float2 g_wfft[N2];     // exp(-2*pi*i*t/4096)
__device__ float2 g_wr  [MODES];  // (cos,sin)(2*pi*k/8192)

// ---------------- tables ----------------
__global__ void init_tables_kernel() {
    int i = blockIdx.x * blockDim.x + threadIdx.x;
    if (i < N2) {
        float s, c;
        sincospif((float)i * (1.0f / 2048.0f), &s, &c);
        g_wfft[i] = make_float2(c, -s);
    }
    if (i < MODES) {
        float s, c;
        sincospif((float)i * (1.0f / 4096.0f), &s, &c);
        g_wr[i] = make_float2(c, s);
    }
}

// ---------------- transpose x: [b,s,c] -> xT [b,c,s] (fp32) ----------------
__global__ void __launch_bounds__(256) transpose_x_kernel(const float* __restrict__ x) {
    __shared__ float t[32][33];
    int b  = blockIdx.z;
    int c0 = blockIdx.x * 32;
    int s0 = blockIdx.y * 32;
    int tx = threadIdx.x, ty = threadIdx.y;
    #pragma unroll
    for (int i = 0; i < 4; i++) {
        int s = s0 + ty + 8 * i;
        t[ty + 8 * i][tx] = x[((size_t)b * SEQ + s) * CH + c0 + tx];
    }
    __syncthreads();
    #pragma unroll
    for (int i = 0; i < 4; i++) {
        int cc = c0 + ty + 8 * i;
        g_xT[((size_t)b * CH + cc) * SEQ + s0 + tx] = t[tx][ty + 8 * i];
    }
}

// ---------------- complex helpers ----------------
__device__ __forceinline__ float2 cadd(float2 a, float2 b) { return make_float2(a.x + b.x, a.y + b.y); }
__device__ __forceinline__ float2 csub(float2 a, float2 b) { return make_float2(a.x - b.x, a.y - b.y); }
__device__ __forceinline__ float2 cmul(float2 a, float2 b) {
    return make_float2(fmaf(a.x, b.x, -a.y * b.y), fmaf(a.x, b.y, a.y * b.x));
}

// forward DFT4 (e^{-i}), in place
__device__ __forceinline__ void dft4(float2& a0, float2& a1, float2& a2, float2& a3) {
    float2 t0 = cadd(a0, a2), t1 = csub(a0, a2);
    float2 t2 = cadd(a1, a3), t3 = csub(a1, a3);
    a0 = cadd(t0, t2);
    a2 = csub(t0, t2);
    a1 = make_float2(t1.x + t3.y, t1.y - t3.x);
    a3 = make_float2(t1.x - t3.y, t1.y + t3.x);
}

// 16-pt DFT in registers; output X[j] lands in v[4*(j&3) + (j>>2)]
__device__ __forceinline__ void dft16(float2 v[16]) {
    #pragma unroll
    for (int i = 0; i < 4; i++) dft4(v[i], v[i + 4], v[i + 8], v[i + 12]);
    const float C1 = 0.92387953251128674f, S1 = 0.38268343236508978f, R = 0.70710678118654752f;
    v[5]  = cmul(make_float2( C1, -S1), v[5]);
    v[6]  = cmul(make_float2(  R,  -R), v[6]);
    v[7]  = cmul(make_float2( S1, -C1), v[7]);
    v[9]  = cmul(make_float2(  R,  -R), v[9]);
    v[10] = make_float2(v[10].y, -v[10].x);
    v[11] = cmul(make_float2( -R,  -R), v[11]);
    v[13] = cmul(make_float2( S1, -C1), v[13]);
    v[14] = cmul(make_float2( -R,  -R), v[14]);
    v[15] = cmul(make_float2(-C1,  S1), v[15]);
    #pragma unroll
    for (int k1 = 0; k1 < 4; k1++) dft4(v[4 * k1], v[4 * k1 + 1], v[4 * k1 + 2], v[4 * k1 + 3]);
}

// ---------------- 4096-pt radix-16 Stockham (forward, e^{-i}), 3 stages -----
__device__ float2* fft4096_r16(float2* A, float2* B) {
    float2* src = A;
    float2* dst = B;
    int ls = 0;
    #pragma unroll
    for (int stage = 0; stage < 3; stage++) {
        int m = 256 >> (4 * stage);
        int idx = threadIdx.x;
        int q = idx & ((1 << ls) - 1);
        int p = idx >> ls;
        float2 v[16];
        #pragma unroll
        for (int j = 0; j < 16; j++)
            v[j] = src[IX(q + ((p + j * m) << ls))];
        dft16(v);
        int twb = p << ls;
        #pragma unroll
        for (int j = 0; j < 16; j++) {
            float2 y = v[4 * (j & 3) + (j >> 2)];
            float2 w = g_wfft[j * twb];
            dst[IX(q + ((16 * p + j) << ls))] = cmul(w, y);
        }
        __syncthreads();
        float2* t = src; src = dst; dst = t;
        ls += 4;
    }
    return src;
}

// ---------------- forward rfft: xT[b,c,s] -> X planar bf16x2 [b*CH+c][k] ----
__global__ void __launch_bounds__(256, 3) fwd_fft_kernel() {
    extern __shared__ char smraw[];
    float2* A = (float2*)smraw;
    float2* B = A + FFT_BUF;
    int row = blockIdx.x;
    const float2* xr = (const float2*)(g_xT + (size_t)row * SEQ);
    for (int j = threadIdx.x; j < 4096; j += 256) {
        A[IX(j)] = xr[j];
    }
    __syncthreads();
    float2* R = fft4096_r16(A, B);
    __nv_bfloat162* X = g_X + (size_t)row * MODES;
    for (int k = threadIdx.x; k <= 4096; k += 256) {
        float2 Zk = R[IX(k & 4095)];
        float2 Zc = R[IX((4096 - k) & 4095)];
        float Ex = 0.5f * (Zk.x + Zc.x), Ey = 0.5f * (Zk.y - Zc.y);
        float Ox = 0.5f * (Zk.x - Zc.x), Oy = 0.5f * (Zk.y + Zc.y);
        float2 w = g_wr[k];
        float re = Ex + w.x * Oy - w.y * Ox;
        float im = Ey - w.x * Ox - w.y * Oy;
        X[k] = __floats2bfloat162_rn(FWD_SCALE * re, FWD_SCALE * im);
    }
}

// ============== tensor-core block-diagonal complex 2-layer MLP ==============
#define MT    256
#define XPAD  98
#define SW_OFF   0                           // 6 * 96 * 98 bf16 = 112896
#define SXR_OFF  (6 * 96 * XPAD * 2)
#define SXI_OFF  (SXR_OFF + MT * XPAD * 2)   // +50176
#define SB_OFF   (SXI_OFF + MT * XPAD * 2)   // +50176
#define MLP_SMEM (SB_OFF + 4 * 96 * 4)       // +1536 = 214784

__device__ __forceinline__ void mma_bf16(float* c, const uint32_t* a, uint32_t b0, uint32_t b1) {
    asm volatile(
        "mma.sync.aligned.m16n8k16.row.col.f32.bf16.bf16.f32 "
        "{%0,%1,%2,%3}, {%4,%5,%6,%7}, {%8,%9}, {%0,%1,%2,%3};"
        : "+f"(c[0]), "+f"(c[1]), "+f"(c[2]), "+f"(c[3])
        : "r"(a[0]), "r"(a[1]), "r"(a[2]), "r"(a[3]), "r"(b0), "r"(b1));
}

__global__ void __launch_bounds__(256) mlp_mma_kernel(const float* __restrict__ w1,
                                                      const float* __restrict__ b1,
                                                      const float* __restrict__ w2,
                                                      const float* __restrict__ b2) {
    extern __shared__ char sm[];
    __nv_bfloat16* s_w  = (__nv_bfloat16*)(sm + SW_OFF);   // [6][96][XPAD]: w1r,w1i,-w1i,w2r,w2i,-w2i
    __nv_bfloat16* s_xr = (__nv_bfloat16*)(sm + SXR_OFF);  // [MT][XPAD]
    __nv_bfloat16* s_xi = (__nv_bfloat16*)(sm + SXI_OFF);
    float*         s_bv = (float*)(sm + SB_OFF);           // [4][96]

    const int tid = threadIdx.x;
    const int n   = blockIdx.y;
    const int b   = blockIdx.z;
    const int m0  = blockIdx.x * MT;

    const float* g_w1r = w1 + n * 9216;
    const float* g_w1i = w1 + 73728 + n * 9216;
    const float* g_w2r = w2 + n * 9216;
    const float* g_w2i = w2 + 73728 + n * 9216;
    for (int i = tid; i < 9216; i += 256) {
        int d = i / 96, k = i % 96;
        int o = k * XPAD + d;
        float v;
        v = g_w1r[i]; s_w[0 * 96 * XPAD + o] = __float2bfloat16_rn(v);
        v = g_w1i[i]; s_w[1 * 96 * XPAD + o] = __float2bfloat16_rn(v);
                      s_w[2 * 96 * XPAD + o] = __float2bfloat16_rn(-v);
        v = g_w2r[i]; s_w[3 * 96 * XPAD + o] = __float2bfloat16_rn(v);
        v = g_w2i[i]; s_w[4 * 96 * XPAD + o] = __float2bfloat16_rn(v);
                      s_w[5 * 96 * XPAD + o] = __float2bfloat16_rn(-v);
    }
    if (tid < 96) {
        s_bv[tid]       = b1[n * 96 + tid];
        s_bv[96 + tid]  = b1[768 + n * 96 + tid];
        s_bv[192 + tid] = b2[n * 96 + tid];
        s_bv[288 + tid] = b2[768 + n * 96 + tid];
    }

    size_t rowbase = ((size_t)b * CH + n * 96) * (size_t)MODES;
    for (int i = tid; i < 96 * MT; i += 256) {
        int d = i >> 8, mm = i & (MT - 1);
        int mode = m0 + mm;
        __nv_bfloat162 xv = (mode < MODES) ? g_X[rowbase + (size_t)d * MODES + mode]
                                           : __nv_bfloat162{__float2bfloat16_rn(0.f), __float2bfloat16_rn(0.f)};
        s_xr[mm * XPAD + d] = xv.x;
        s_xi[mm * XPAD + d] = xv.y;
    }
    __syncthreads();

    const int lane = tid & 31;
    const int warp = tid >> 5;
    const int g  = lane >> 2;
    const int t  = lane & 3;

    const uint32_t* Ww = (const uint32_t*)s_w;
    const uint32_t* Xr = (const uint32_t*)s_xr;
    const uint32_t* Xi = (const uint32_t*)s_xi;
    const int RS = XPAD / 2;   // 49

    for (int h = 0; h < 2; h++) {
        const int mrow = warp * 32 + h * 16;
        float cr[12][4], ci[12][4];

        // ---------- layer 1 ----------
        #pragma unroll
        for (int nt = 0; nt < 12; nt++) {
            float br0 = s_bv[nt * 8 + 2 * t], br1 = s_bv[nt * 8 + 2 * t + 1];
            float bi0 = s_bv[96 + nt * 8 + 2 * t], bi1 = s_bv[96 + nt * 8 + 2 * t + 1];
            cr[nt][0] = br0; cr[nt][1] = br1; cr[nt][2] = br0; cr[nt][3] = br1;
            ci[nt][0] = bi0; ci[nt][1] = bi1; ci[nt][2] = bi0; ci[nt][3] = bi1;
        }
        #pragma unroll
        for (int k = 0; k < 6; k++) {
            int kw = k * 8 + t;
            uint32_t ar[4], ai[4];
            ar[0] = Xr[(mrow + g) * RS + kw];     ar[1] = Xr[(mrow + g + 8) * RS + kw];
            ar[2] = Xr[(mrow + g) * RS + kw + 4]; ar[3] = Xr[(mrow + g + 8) * RS + kw + 4];
            ai[0] = Xi[(mrow + g) * RS + kw];     ai[1] = Xi[(mrow + g + 8) * RS + kw];
            ai[2] = Xi[(mrow + g) * RS + kw + 4]; ai[3] = Xi[(mrow + g + 8) * RS + kw + 4];
            #pragma unroll
            for (int nt = 0; nt < 12; nt++) {
                int wrow = (nt * 8 + g) * RS + kw;
                uint32_t wr0  = Ww[0 * 96 * RS + wrow], wr1  = Ww[0 * 96 * RS + wrow + 4];
                uint32_t wi0  = Ww[1 * 96 * RS + wrow], wi1  = Ww[1 * 96 * RS + wrow + 4];
                uint32_t nwi0 = Ww[2 * 96 * RS + wrow], nwi1 = Ww[2 * 96 * RS + wrow + 4];
                mma_bf16(cr[nt], ar, wr0, wr1);
                mma_bf16(cr[nt], ai, nwi0, nwi1);
                mma_bf16(ci[nt], ai, wr0, wr1);
                mma_bf16(ci[nt], ar, wi0, wi1);
            }
        }
        __syncwarp();
        {
            uint32_t* Xrw = (uint32_t*)s_xr;
            uint32_t* Xiw = (uint32_t*)s_xi;
            #pragma unroll
            for (int nt = 0; nt < 12; nt++) {
                int cw = nt * 4 + t;
                __nv_bfloat162 hh;
                hh = __floats2bfloat162_rn(fmaxf(cr[nt][0], 0.0f), fmaxf(cr[nt][1], 0.0f));
                Xrw[(mrow + g) * RS + cw] = *(uint32_t*)&hh;
                hh = __floats2bfloat162_rn(fmaxf(cr[nt][2], 0.0f), fmaxf(cr[nt][3], 0.0f));
                Xrw[(mrow + g + 8) * RS + cw] = *(uint32_t*)&hh;
                hh = __floats2bfloat162_rn(fmaxf(ci[nt][0], 0.0f), fmaxf(ci[nt][1], 0.0f));
                Xiw[(mrow + g) * RS + cw] = *(uint32_t*)&hh;
                hh = __floats2bfloat162_rn(fmaxf(ci[nt][2], 0.0f), fmaxf(ci[nt][3], 0.0f));
                Xiw[(mrow + g + 8) * RS + cw] = *(uint32_t*)&hh;
            }
        }
        __syncwarp();

        // ---------- layer 2 ----------
        #pragma unroll
        for (int nt = 0; nt < 12; nt++) {
            float br0 = s_bv[192 + nt * 8 + 2 * t], br1 = s_bv[192 + nt * 8 + 2 * t + 1];
            float bi0 = s_bv[288 + nt * 8 + 2 * t], bi1 = s_bv[288 + nt * 8 + 2 * t + 1];
            cr[nt][0] = br0; cr[nt][1] = br1; cr[nt][2] = br0; cr[nt][3] = br1;
            ci[nt][0] = bi0; ci[nt][1] = bi1; ci[nt][2] = bi0; ci[nt][3] = bi1;
        }
        #pragma unroll
        for (int k = 0; k < 6; k++) {
            int kw = k * 8 + t;
            uint32_t ar[4], ai[4];
            ar[0] = Xr[(mrow + g) * RS + kw];     ar[1] = Xr[(mrow + g + 8) * RS + kw];
            ar[2] = Xr[(mrow + g) * RS + kw + 4]; ar[3] = Xr[(mrow + g + 8) * RS + kw + 4];
            ai[0] = Xi[(mrow + g) * RS + kw];     ai[1] = Xi[(mrow + g + 8) * RS + kw];
            ai[2] = Xi[(mrow + g) * RS + kw + 4]; ai[3] = Xi[(mrow + g + 8) * RS + kw + 4];
            #pragma unroll
            for (int nt = 0; nt < 12; nt++) {
                int wrow = (nt * 8 + g) * RS + kw;
                uint32_t wr0  = Ww[3 * 96 * RS + wrow], wr1  = Ww[3 * 96 * RS + wrow + 4];
                uint32_t wi0  = Ww[4 * 96 * RS + wrow], wi1  = Ww[4 * 96 * RS + wrow + 4];
                uint32_t nwi0 = Ww[5 * 96 * RS + wrow], nwi1 = Ww[5 * 96 * RS + wrow + 4];
                mma_bf16(cr[nt], ar, wr0, wr1);
                mma_bf16(cr[nt], ai, nwi0, nwi1);
                mma_bf16(ci[nt], ai, wr0, wr1);
                mma_bf16(ci[nt], ar, wi0, wi1);
            }
        }

        // ---------- softshrink + store (bf16x2) ----------
        int mode_lo = m0 + mrow + g;
        int mode_hi = mode_lo + 8;
        #pragma unroll
        for (int nt = 0; nt < 12; nt++) {
            #pragma unroll
            for (int j = 0; j < 4; j++) {
                int col  = nt * 8 + 2 * t + (j & 1);
                int mode = (j < 2) ? mode_lo : mode_hi;
                if (mode < MODES) {
                    size_t off = rowbase + (size_t)col * MODES + mode;
                    float vr = cr[nt][j];
                    float vi = ci[nt][j];
                    vr = copysignf(fmaxf(fabsf(vr) - LAM, 0.0f), vr);
                    vi = copysignf(fmaxf(fabsf(vi) - LAM, 0.0f), vi);
                    g_X[off] = __floats2bfloat162_rn(vr, vi);
                }
            }
        }
    }
}

// ---------------- inverse rfft: X planar bf16x2 -> yT bf16 [b*CH+c][s] ------
__global__ void __launch_bounds__(256, 3) inv_fft_kernel() {
    extern __shared__ char smraw[];
    float2* A = (float2*)smraw;
    float2* B = A + FFT_BUF;
    int row = blockIdx.x;
    const __nv_bfloat162* X = g_X + (size_t)row * MODES;
    for (int k = threadIdx.x; k < 4096; k += 256) {
        __nv_bfloat162 xk = X[k];
        __nv_bfloat162 xc = X[4096 - k];
        float xkr = __bfloat162float(xk.x), xki = __bfloat162float(xk.y);
        float xcr = __bfloat162float(xc.x), xci = __bfloat162float(xc.y);
        if (k == 0) { xki = 0.0f; xci = 0.0f; }
        float Ex = 0.5f * (xkr + xcr), Ey = 0.5f * (xki - xci);
        float Gx = 0.5f * (xkr - xcr), Gy = 0.5f * (xki + xci);
        float2 w = g_wr[k];
        float WOx = w.x * Gx - w.y * Gy;
        float WOy = w.x * Gy + w.y * Gx;
        float Zx = Ex - WOy;
        float Zy = Ey + WOx;
        A[IX(k)] = make_float2(INV_SCALE * Zx, -INV_SCALE * Zy);
    }
    __syncthreads();
    float2* R = fft4096_r16(A, B);
    __nv_bfloat162* out = (__nv_bfloat162*)(g_yT + (size_t)row * SEQ);
    for (int j = threadIdx.x; j < 4096; j += 256) {
        float2 r = R[IX(j)];
        out[j] = __floats2bfloat162_rn(r.x, -r.y);
    }
}

// ---------------- transpose + bias: out[b,s,c] = x[b,s,c] + yT[b,c,s] -------
__global__ void __launch_bounds__(256) final_kernel(const float* __restrict__ x,
                                                    float* __restrict__ out) {
    __shared__ float t[32][33];
    int b  = blockIdx.z;
    int c0 = blockIdx.x * 32;
    int s0 = blockIdx.y * 32;
    int tx = threadIdx.x, ty = threadIdx.y;
    #pragma unroll
    for (int i = 0; i < 4; i++) {
        int cc = c0 + ty + 8 * i;
        t[ty + 8 * i][tx] = __bfloat162float(g_yT[((size_t)b * CH + cc) * SEQ + s0 + tx]);
    }
    __syncthreads();
    #pragma unroll
    for (int i = 0; i < 4; i++) {
        int s = s0 + ty + 8 * i;
        size_t off = ((size_t)b * SEQ + s) * CH + c0 + tx;
        out[off] = x[off] + t[tx][ty + 8 * i];
    }
}

// ---------------- launcher ----------------
extern "C" void kernel_launch(void* const* d_in, const int* in_sizes, int n_in,
                              void* d_out, int out_size) {
    const float* x  = (const float*)d_in[0];
    const float* w1 = (const float*)d_in[1];
    const float* b1 = (const float*)d_in[2];
    const float* w2 = (const float*)d_in[3];
    const float* b2 = (const float*)d_in[4];
    float* out = (float*)d_out;

    cudaFuncSetAttribute(fwd_fft_kernel, cudaFuncAttributeMaxDynamicSharedMemorySize, FFT_SMEM);
    cudaFuncSetAttribute(inv_fft_kernel, cudaFuncAttributeMaxDynamicSharedMemorySize, FFT_SMEM);
    cudaFuncSetAttribute(mlp_mma_kernel, cudaFuncAttributeMaxDynamicSharedMemorySize, MLP_SMEM);

    init_tables_kernel<<<17, 256>>>();
    transpose_x_kernel<<<dim3(CH / 32, SEQ / 32, BATCH), dim3(32, 8)>>>(x);
    fwd_fft_kernel<<<BATCH * CH, 256, FFT_SMEM>>>();
    mlp_mma_kernel<<<dim3((MODES + MT - 1) / MT, NBLK, BATCH), 256, MLP_SMEM>>>(w1, b1, w2, b2);
    inv_fft_kernel<<<BATCH * CH, 256, FFT_SMEM>>>();
    final_kernel<<<dim3(CH / 32, SEQ / 32, BATCH), dim3(32, 8)>>>(x, out);
}

// round 9
// speedup vs baseline: 1.4746x; 1.0492x over previous
#include <cuda_runtime.h>
#include <cuda_bf16.h>
#include <math.h>
#include <stdint.h>

#define BATCH 4
#define SEQ   8192
#define CH    768
#define N2    4096
#define MODES 4097
#define NBLK  8
#define LAM   0.01f

#define FWD_SCALE 0.011048543456039806f   // 1/sqrt(8192)
#define INV_SCALE 0.022097086912079613f   // sqrt(8192)/4096

// padded smem indexing: 1 extra float2 per 32 -> kills 128B-stride conflicts
#define IX(i) ((i) + ((i) >> 5))
#define FFT_BUF 4224
#define FFT_SMEM (2 * FFT_BUF * 8)        // 67584 bytes

// ---------------- device scratch ----------------
__device__ float          g_xT[BATCH * CH * SEQ];        // x transposed [b][c][s], fp32
__device__ __nv_bfloat162 g_X [BATCH * CH * MODES];      // spectrum (re,im) bf16x2
__device__ __nv_bfloat16  g_yT[BATCH * CH * SEQ];        // irfft out [b][c][s]
__device__ float2 g_wfft[N2];     // exp(-2*pi*i*t/4096)
__device__ float2 g_wr  [MODES];  // (cos,sin)(2*pi*k/8192)

// ---------------- tables ----------------
__global__ void init_tables_kernel() {
    int i = blockIdx.x * blockDim.x + threadIdx.x;
    if (i < N2) {
        float s, c;
        sincospif((float)i * (1.0f / 2048.0f), &s, &c);
        g_wfft[i] = make_float2(c, -s);
    }
    if (i < MODES) {
        float s, c;
        sincospif((float)i * (1.0f / 4096.0f), &s, &c);
        g_wr[i] = make_float2(c, s);
    }
}

// ---------------- transpose x: [b,s,c] -> xT [b,c,s] (fp32) ----------------
__global__ void __launch_bounds__(256) transpose_x_kernel(const float* __restrict__ x) {
    __shared__ float t[32][33];
    int b  = blockIdx.z;
    int c0 = blockIdx.x * 32;
    int s0 = blockIdx.y * 32;
    int tx = threadIdx.x, ty = threadIdx.y;
    #pragma unroll
    for (int i = 0; i < 4; i++) {
        int s = s0 + ty + 8 * i;
        t[ty + 8 * i][tx] = x[((size_t)b * SEQ + s) * CH + c0 + tx];
    }
    __syncthreads();
    #pragma unroll
    for (int i = 0; i < 4; i++) {
        int cc = c0 + ty + 8 * i;
        g_xT[((size_t)b * CH + cc) * SEQ + s0 + tx] = t[tx][ty + 8 * i];
    }
}

// ---------------- complex helpers ----------------
__device__ __forceinline__ float2 cadd(float2 a, float2 b) { return make_float2(a.x + b.x, a.y + b.y); }
__device__ __forceinline__ float2 csub(float2 a, float2 b) { return make_float2(a.x - b.x, a.y - b.y); }
__device__ __forceinline__ float2 cmul(float2 a, float2 b) {
    return make_float2(fmaf(a.x, b.x, -a.y * b.y), fmaf(a.x, b.y, a.y * b.x));
}

// forward DFT4 (e^{-i}), in place
__device__ __forceinline__ void dft4(float2& a0, float2& a1, float2& a2, float2& a3) {
    float2 t0 = cadd(a0, a2), t1 = csub(a0, a2);
    float2 t2 = cadd(a1, a3), t3 = csub(a1, a3);
    a0 = cadd(t0, t2);
    a2 = csub(t0, t2);
    a1 = make_float2(t1.x + t3.y, t1.y - t3.x);
    a3 = make_float2(t1.x - t3.y, t1.y + t3.x);
}

// 16-pt DFT in registers; output X[j] lands in v[4*(j&3) + (j>>2)]
__device__ __forceinline__ void dft16(float2 v[16]) {
    #pragma unroll
    for (int i = 0; i < 4; i++) dft4(v[i], v[i + 4], v[i + 8], v[i + 12]);
    const float C1 = 0.92387953251128674f, S1 = 0.38268343236508978f, R = 0.70710678118654752f;
    v[5]  = cmul(make_float2( C1, -S1), v[5]);
    v[6]  = cmul(make_float2(  R,  -R), v[6]);
    v[7]  = cmul(make_float2( S1, -C1), v[7]);
    v[9]  = cmul(make_float2(  R,  -R), v[9]);
    v[10] = make_float2(v[10].y, -v[10].x);
    v[11] = cmul(make_float2( -R,  -R), v[11]);
    v[13] = cmul(make_float2( S1, -C1), v[13]);
    v[14] = cmul(make_float2( -R,  -R), v[14]);
    v[15] = cmul(make_float2(-C1,  S1), v[15]);
    #pragma unroll
    for (int k1 = 0; k1 < 4; k1++) dft4(v[4 * k1], v[4 * k1 + 1], v[4 * k1 + 2], v[4 * k1 + 3]);
}

// ---------------- 4096-pt radix-16 Stockham (forward, e^{-i}), 3 stages -----
__device__ float2* fft4096_r16(float2* A, float2* B) {
    float2* src = A;
    float2* dst = B;
    int ls = 0;
    #pragma unroll
    for (int stage = 0; stage < 3; stage++) {
        int m = 256 >> (4 * stage);
        int idx = threadIdx.x;
        int q = idx & ((1 << ls) - 1);
        int p = idx >> ls;
        float2 v[16];
        #pragma unroll
        for (int j = 0; j < 16; j++)
            v[j] = src[IX(q + ((p + j * m) << ls))];
        dft16(v);
        int twb = p << ls;
        #pragma unroll
        for (int j = 0; j < 16; j++) {
            float2 y = v[4 * (j & 3) + (j >> 2)];
            float2 w = g_wfft[j * twb];
            dst[IX(q + ((16 * p + j) << ls))] = cmul(w, y);
        }
        __syncthreads();
        float2* t = src; src = dst; dst = t;
        ls += 4;
    }
    return src;
}

// ---------------- forward rfft: xT[b,c,s] -> X planar bf16x2 [b*CH+c][k] ----
__global__ void __launch_bounds__(256, 3) fwd_fft_kernel() {
    extern __shared__ char smraw[];
    float2* A = (float2*)smraw;
    float2* B = A + FFT_BUF;
    int row = blockIdx.x;
    const float2* xr = (const float2*)(g_xT + (size_t)row * SEQ);
    for (int j = threadIdx.x; j < 4096; j += 256) {
        A[IX(j)] = xr[j];
    }
    __syncthreads();
    float2* R = fft4096_r16(A, B);
    __nv_bfloat162* X = g_X + (size_t)row * MODES;
    for (int k = threadIdx.x; k <= 4096; k += 256) {
        float2 Zk = R[IX(k & 4095)];
        float2 Zc = R[IX((4096 - k) & 4095)];
        float Ex = 0.5f * (Zk.x + Zc.x), Ey = 0.5f * (Zk.y - Zc.y);
        float Ox = 0.5f * (Zk.x - Zc.x), Oy = 0.5f * (Zk.y + Zc.y);
        float2 w = g_wr[k];
        float re = Ex + w.x * Oy - w.y * Ox;
        float im = Ey - w.x * Ox - w.y * Oy;
        X[k] = __floats2bfloat162_rn(FWD_SCALE * re, FWD_SCALE * im);
    }
}

// ============== tensor-core block-diagonal complex 2-layer MLP ==============
// CTA = (mode-tile of 256, block n, batch b). 512 threads; 16 warps x 16 modes.
#define MT    256
#define MLP_THREADS 512
#define XPAD  98
#define SW_OFF   0                           // 6 * 96 * 98 bf16 = 112896
#define SXR_OFF  (6 * 96 * XPAD * 2)
#define SXI_OFF  (SXR_OFF + MT * XPAD * 2)   // +50176
#define SB_OFF   (SXI_OFF + MT * XPAD * 2)   // +50176
#define MLP_SMEM (SB_OFF + 4 * 96 * 4)       // +1536 = 214784

__device__ __forceinline__ void mma_bf16(float* c, const uint32_t* a, uint32_t b0, uint32_t b1) {
    asm volatile(
        "mma.sync.aligned.m16n8k16.row.col.f32.bf16.bf16.f32 "
        "{%0,%1,%2,%3}, {%4,%5,%6,%7}, {%8,%9}, {%0,%1,%2,%3};"
        : "+f"(c[0]), "+f"(c[1]), "+f"(c[2]), "+f"(c[3])
        : "r"(a[0]), "r"(a[1]), "r"(a[2]), "r"(a[3]), "r"(b0), "r"(b1));
}

__global__ void __launch_bounds__(MLP_THREADS) mlp_mma_kernel(const float* __restrict__ w1,
                                                              const float* __restrict__ b1,
                                                              const float* __restrict__ w2,
                                                              const float* __restrict__ b2) {
    extern __shared__ char sm[];
    __nv_bfloat16* s_w  = (__nv_bfloat16*)(sm + SW_OFF);   // [6][96][XPAD]: w1r,w1i,-w1i,w2r,w2i,-w2i
    __nv_bfloat16* s_xr = (__nv_bfloat16*)(sm + SXR_OFF);  // [MT][XPAD]
    __nv_bfloat16* s_xi = (__nv_bfloat16*)(sm + SXI_OFF);
    float*         s_bv = (float*)(sm + SB_OFF);           // [4][96]

    const int tid = threadIdx.x;
    const int n   = blockIdx.y;
    const int b   = blockIdx.z;
    const int m0  = blockIdx.x * MT;

    const float* g_w1r = w1 + n * 9216;
    const float* g_w1i = w1 + 73728 + n * 9216;
    const float* g_w2r = w2 + n * 9216;
    const float* g_w2i = w2 + 73728 + n * 9216;
    for (int i = tid; i < 9216; i += MLP_THREADS) {
        int d = i / 96, k = i % 96;
        int o = k * XPAD + d;
        float v;
        v = g_w1r[i]; s_w[0 * 96 * XPAD + o] = __float2bfloat16_rn(v);
        v = g_w1i[i]; s_w[1 * 96 * XPAD + o] = __float2bfloat16_rn(v);
                      s_w[2 * 96 * XPAD + o] = __float2bfloat16_rn(-v);
        v = g_w2r[i]; s_w[3 * 96 * XPAD + o] = __float2bfloat16_rn(v);
        v = g_w2i[i]; s_w[4 * 96 * XPAD + o] = __float2bfloat16_rn(v);
                      s_w[5 * 96 * XPAD + o] = __float2bfloat16_rn(-v);
    }
    if (tid < 96) {
        s_bv[tid]       = b1[n * 96 + tid];
        s_bv[96 + tid]  = b1[768 + n * 96 + tid];
        s_bv[192 + tid] = b2[n * 96 + tid];
        s_bv[288 + tid] = b2[768 + n * 96 + tid];
    }

    size_t rowbase = ((size_t)b * CH + n * 96) * (size_t)MODES;
    for (int i = tid; i < 96 * MT; i += MLP_THREADS) {
        int d = i >> 8, mm = i & (MT - 1);
        int mode = m0 + mm;
        __nv_bfloat162 xv = (mode < MODES) ? g_X[rowbase + (size_t)d * MODES + mode]
                                           : __nv_bfloat162{__float2bfloat16_rn(0.f), __float2bfloat16_rn(0.f)};
        s_xr[mm * XPAD + d] = xv.x;
        s_xi[mm * XPAD + d] = xv.y;
    }
    __syncthreads();

    const int lane = tid & 31;
    const int warp = tid >> 5;           // 0..15
    const int g  = lane >> 2;
    const int t  = lane & 3;
    const int mrow = warp * 16;          // each warp owns 16 modes

    const uint32_t* Ww = (const uint32_t*)s_w;
    const uint32_t* Xr = (const uint32_t*)s_xr;
    const uint32_t* Xi = (const uint32_t*)s_xi;
    const int RS = XPAD / 2;   // 49

    float cr[12][4], ci[12][4];

    // ---------- layer 1 ----------
    #pragma unroll
    for (int nt = 0; nt < 12; nt++) {
        float br0 = s_bv[nt * 8 + 2 * t], br1 = s_bv[nt * 8 + 2 * t + 1];
        float bi0 = s_bv[96 + nt * 8 + 2 * t], bi1 = s_bv[96 + nt * 8 + 2 * t + 1];
        cr[nt][0] = br0; cr[nt][1] = br1; cr[nt][2] = br0; cr[nt][3] = br1;
        ci[nt][0] = bi0; ci[nt][1] = bi1; ci[nt][2] = bi0; ci[nt][3] = bi1;
    }
    #pragma unroll
    for (int k = 0; k < 6; k++) {
        int kw = k * 8 + t;
        uint32_t ar[4], ai[4];
        ar[0] = Xr[(mrow + g) * RS + kw];     ar[1] = Xr[(mrow + g + 8) * RS + kw];
        ar[2] = Xr[(mrow + g) * RS + kw + 4]; ar[3] = Xr[(mrow + g + 8) * RS + kw + 4];
        ai[0] = Xi[(mrow + g) * RS + kw];     ai[1] = Xi[(mrow + g + 8) * RS + kw];
        ai[2] = Xi[(mrow + g) * RS + kw + 4]; ai[3] = Xi[(mrow + g + 8) * RS + kw + 4];
        #pragma unroll
        for (int nt = 0; nt < 12; nt++) {
            int wrow = (nt * 8 + g) * RS + kw;
            uint32_t wr0  = Ww[0 * 96 * RS + wrow], wr1  = Ww[0 * 96 * RS + wrow + 4];
            uint32_t wi0  = Ww[1 * 96 * RS + wrow], wi1  = Ww[1 * 96 * RS + wrow + 4];
            uint32_t nwi0 = Ww[2 * 96 * RS + wrow], nwi1 = Ww[2 * 96 * RS + wrow + 4];
            mma_bf16(cr[nt], ar, wr0, wr1);
            mma_bf16(cr[nt], ai, nwi0, nwi1);
            mma_bf16(ci[nt], ai, wr0, wr1);
            mma_bf16(ci[nt], ar, wi0, wi1);
        }
    }
    __syncwarp();
    {
        uint32_t* Xrw = (uint32_t*)s_xr;
        uint32_t* Xiw = (uint32_t*)s_xi;
        #pragma unroll
        for (int nt = 0; nt < 12; nt++) {
            int cw = nt * 4 + t;
            __nv_bfloat162 hh;
            hh = __floats2bfloat162_rn(fmaxf(cr[nt][0], 0.0f), fmaxf(cr[nt][1], 0.0f));
            Xrw[(mrow + g) * RS + cw] = *(uint32_t*)&hh;
            hh = __floats2bfloat162_rn(fmaxf(cr[nt][2], 0.0f), fmaxf(cr[nt][3], 0.0f));
            Xrw[(mrow + g + 8) * RS + cw] = *(uint32_t*)&hh;
            hh = __floats2bfloat162_rn(fmaxf(ci[nt][0], 0.0f), fmaxf(ci[nt][1], 0.0f));
            Xiw[(mrow + g) * RS + cw] = *(uint32_t*)&hh;
            hh = __floats2bfloat162_rn(fmaxf(ci[nt][2], 0.0f), fmaxf(ci[nt][3], 0.0f));
            Xiw[(mrow + g + 8) * RS + cw] = *(uint32_t*)&hh;
        }
    }
    __syncwarp();

    // ---------- layer 2 ----------
    #pragma unroll
    for (int nt = 0; nt < 12; nt++) {
        float br0 = s_bv[192 + nt * 8 + 2 * t], br1 = s_bv[192 + nt * 8 + 2 * t + 1];
        float bi0 = s_bv[288 + nt * 8 + 2 * t], bi1 = s_bv[288 + nt * 8 + 2 * t + 1];
        cr[nt][0] = br0; cr[nt][1] = br1; cr[nt][2] = br0; cr[nt][3] = br1;
        ci[nt][0] = bi0; ci[nt][1] = bi1; ci[nt][2] = bi0; ci[nt][3] = bi1;
    }
    #pragma unroll
    for (int k = 0; k < 6; k++) {
        int kw = k * 8 + t;
        uint32_t ar[4], ai[4];
        ar[0] = Xr[(mrow + g) * RS + kw];     ar[1] = Xr[(mrow + g + 8) * RS + kw];
        ar[2] = Xr[(mrow + g) * RS + kw + 4]; ar[3] = Xr[(mrow + g + 8) * RS + kw + 4];
        ai[0] = Xi[(mrow + g) * RS + kw];     ai[1] = Xi[(mrow + g + 8) * RS + kw];
        ai[2] = Xi[(mrow + g) * RS + kw + 4]; ai[3] = Xi[(mrow + g + 8) * RS + kw + 4];
        #pragma unroll
        for (int nt = 0; nt < 12; nt++) {
            int wrow = (nt * 8 + g) * RS + kw;
            uint32_t wr0  = Ww[3 * 96 * RS + wrow], wr1  = Ww[3 * 96 * RS + wrow + 4];
            uint32_t wi0  = Ww[4 * 96 * RS + wrow], wi1  = Ww[4 * 96 * RS + wrow + 4];
            uint32_t nwi0 = Ww[5 * 96 * RS + wrow], nwi1 = Ww[5 * 96 * RS + wrow + 4];
            mma_bf16(cr[nt], ar, wr0, wr1);
            mma_bf16(cr[nt], ai, nwi0, nwi1);
            mma_bf16(ci[nt], ai, wr0, wr1);
            mma_bf16(ci[nt], ar, wi0, wi1);
        }
    }

    // ---------- softshrink + store (bf16x2) ----------
    int mode_lo = m0 + mrow + g;
    int mode_hi = mode_lo + 8;
    #pragma unroll
    for (int nt = 0; nt < 12; nt++) {
        #pragma unroll
        for (int j = 0; j < 4; j++) {
            int col  = nt * 8 + 2 * t + (j & 1);
            int mode = (j < 2) ? mode_lo : mode_hi;
            if (mode < MODES) {
                size_t off = rowbase + (size_t)col * MODES + mode;
                float vr = cr[nt][j];
                float vi = ci[nt][j];
                vr = copysignf(fmaxf(fabsf(vr) - LAM, 0.0f), vr);
                vi = copysignf(fmaxf(fabsf(vi) - LAM, 0.0f), vi);
                g_X[off] = __floats2bfloat162_rn(vr, vi);
            }
        }
    }
}

// ---------------- inverse rfft: X planar bf16x2 -> yT bf16 [b*CH+c][s] ------
__global__ void __launch_bounds__(256, 3) inv_fft_kernel() {
    extern __shared__ char smraw[];
    float2* A = (float2*)smraw;
    float2* B = A + FFT_BUF;
    int row = blockIdx.x;
    const __nv_bfloat162* X = g_X + (size_t)row * MODES;
    for (int k = threadIdx.x; k < 4096; k += 256) {
        __nv_bfloat162 xk = X[k];
        __nv_bfloat162 xc = X[4096 - k];
        float xkr = __bfloat162float(xk.x), xki = __bfloat162float(xk.y);
        float xcr = __bfloat162float(xc.x), xci = __bfloat162float(xc.y);
        if (k == 0) { xki = 0.0f; xci = 0.0f; }
        float Ex = 0.5f * (xkr + xcr), Ey = 0.5f * (xki - xci);
        float Gx = 0.5f * (xkr - xcr), Gy = 0.5f * (xki + xci);
        float2 w = g_wr[k];
        float WOx = w.x * Gx - w.y * Gy;
        float WOy = w.x * Gy + w.y * Gx;
        float Zx = Ex - WOy;
        float Zy = Ey + WOx;
        A[IX(k)] = make_float2(INV_SCALE * Zx, -INV_SCALE * Zy);
    }
    __syncthreads();
    float2* R = fft4096_r16(A, B);
    __nv_bfloat162* out = (__nv_bfloat162*)(g_yT + (size_t)row * SEQ);
    for (int j = threadIdx.x; j < 4096; j += 256) {
        float2 r = R[IX(j)];
        out[j] = __floats2bfloat162_rn(r.x, -r.y);
    }
}

// ---------------- transpose + bias: out[b,s,c] = x[b,s,c] + yT[b,c,s] -------
__global__ void __launch_bounds__(256) final_kernel(const float* __restrict__ x,
                                                    float* __restrict__ out) {
    __shared__ float t[32][33];
    int b  = blockIdx.z;
    int c0 = blockIdx.x * 32;
    int s0 = blockIdx.y * 32;
    int tx = threadIdx.x, ty = threadIdx.y;
    #pragma unroll
    for (int i = 0; i < 4; i++) {
        int cc = c0 + ty + 8 * i;
        t[ty + 8 * i][tx] = __bfloat162float(g_yT[((size_t)b * CH + cc) * SEQ + s0 + tx]);
    }
    __syncthreads();
    #pragma unroll
    for (int i = 0; i < 4; i++) {
        int s = s0 + ty + 8 * i;
        size_t off = ((size_t)b * SEQ + s) * CH + c0 + tx;
        out[off] = x[off] + t[tx][ty + 8 * i];
    }
}

// ---------------- launcher ----------------
extern "C" void kernel_launch(void* const* d_in, const int* in_sizes, int n_in,
                              void* d_out, int out_size) {
    const float* x  = (const float*)d_in[0];
    const float* w1 = (const float*)d_in[1];
    const float* b1 = (const float*)d_in[2];
    const float* w2 = (const float*)d_in[3];
    const float* b2 = (const float*)d_in[4];
    float* out = (float*)d_out;

    cudaFuncSetAttribute(fwd_fft_kernel, cudaFuncAttributeMaxDynamicSharedMemorySize, FFT_SMEM);
    cudaFuncSetAttribute(inv_fft_kernel, cudaFuncAttributeMaxDynamicSharedMemorySize, FFT_SMEM);
    cudaFuncSetAttribute(mlp_mma_kernel, cudaFuncAttributeMaxDynamicSharedMemorySize, MLP_SMEM);

    init_tables_kernel<<<17, 256>>>();
    transpose_x_kernel<<<dim3(CH / 32, SEQ / 32, BATCH), dim3(32, 8)>>>(x);
    fwd_fft_kernel<<<BATCH * CH, 256, FFT_SMEM>>>();
    mlp_mma_kernel<<<dim3((MODES + MT - 1) / MT, NBLK, BATCH), MLP_THREADS, MLP_SMEM>>>(w1, b1, w2, b2);
    inv_fft_kernel<<<BATCH * CH, 256, FFT_SMEM>>>();
    final_kernel<<<dim3(CH / 32, SEQ / 32, BATCH), dim3(32, 8)>>>(x, out);
}

// round 11
// speedup vs baseline: 1.4948x; 1.0137x over previous
#include <cuda_runtime.h>
#include <cuda_bf16.h>
#include <math.h>
#include <stdint.h>

#define BATCH 4
#define SEQ   8192
#define CH    768
#define N2    4096
#define MODES 4097
#define NBLK  8
#define LAM   0.01f

#define FWD_SCALE 0.011048543456039806f   // 1/sqrt(8192)
#define INV_SCALE 0.022097086912079613f   // sqrt(8192)/4096

// padded smem indexing: 1 extra float2 per 32 -> kills 128B-stride conflicts
#define IX(i) ((i) + ((i) >> 5))
#define FFT_BUF 4224
#define FFT_SMEM (2 * FFT_BUF * 8)        // 67584 bytes

// ---------------- device scratch ----------------
__device__ float          g_xT[BATCH * CH * SEQ];        // x transposed [b][c][s], fp32
__device__ __nv_bfloat162 g_X [BATCH * CH * MODES];      // spectrum (re,im) bf16x2
__device__ __nv_bfloat16  g_yT[BATCH * CH * SEQ];        // irfft out [b][c][s]
__device__ float2 g_wfft[N2];     // exp(-2*pi*i*t/4096)
__device__ float2 g_wr  [MODES];  // (cos,sin)(2*pi*k/8192)

// ---------------- tables ----------------
__global__ void init_tables_kernel() {
    int i = blockIdx.x * blockDim.x + threadIdx.x;
    if (i < N2) {
        float s, c;
        sincospif((float)i * (1.0f / 2048.0f), &s, &c);
        g_wfft[i] = make_float2(c, -s);
    }
    if (i < MODES) {
        float s, c;
        sincospif((float)i * (1.0f / 4096.0f), &s, &c);
        g_wr[i] = make_float2(c, s);
    }
}

// ---------------- transpose x: [b,s,c] -> xT [b,c,s] (fp32) ----------------
__global__ void __launch_bounds__(256) transpose_x_kernel(const float* __restrict__ x) {
    __shared__ float t[32][33];
    int b  = blockIdx.z;
    int c0 = blockIdx.x * 32;
    int s0 = blockIdx.y * 32;
    int tx = threadIdx.x, ty = threadIdx.y;
    #pragma unroll
    for (int i = 0; i < 4; i++) {
        int s = s0 + ty + 8 * i;
        t[ty + 8 * i][tx] = x[((size_t)b * SEQ + s) * CH + c0 + tx];
    }
    __syncthreads();
    #pragma unroll
    for (int i = 0; i < 4; i++) {
        int cc = c0 + ty + 8 * i;
        g_xT[((size_t)b * CH + cc) * SEQ + s0 + tx] = t[tx][ty + 8 * i];
    }
}

// ---------------- complex helpers ----------------
__device__ __forceinline__ float2 cadd(float2 a, float2 b) { return make_float2(a.x + b.x, a.y + b.y); }
__device__ __forceinline__ float2 csub(float2 a, float2 b) { return make_float2(a.x - b.x, a.y - b.y); }
__device__ __forceinline__ float2 cmul(float2 a, float2 b) {
    return make_float2(fmaf(a.x, b.x, -a.y * b.y), fmaf(a.x, b.y, a.y * b.x));
}

// forward DFT4 (e^{-i}), in place
__device__ __forceinline__ void dft4(float2& a0, float2& a1, float2& a2, float2& a3) {
    float2 t0 = cadd(a0, a2), t1 = csub(a0, a2);
    float2 t2 = cadd(a1, a3), t3 = csub(a1, a3);
    a0 = cadd(t0, t2);
    a2 = csub(t0, t2);
    a1 = make_float2(t1.x + t3.y, t1.y - t3.x);
    a3 = make_float2(t1.x - t3.y, t1.y + t3.x);
}

// 16-pt DFT in registers; output X[j] lands in v[4*(j&3) + (j>>2)]
__device__ __forceinline__ void dft16(float2 v[16]) {
    #pragma unroll
    for (int i = 0; i < 4; i++) dft4(v[i], v[i + 4], v[i + 8], v[i + 12]);
    const float C1 = 0.92387953251128674f, S1 = 0.38268343236508978f, R = 0.70710678118654752f;
    v[5]  = cmul(make_float2( C1, -S1), v[5]);
    v[6]  = cmul(make_float2(  R,  -R), v[6]);
    v[7]  = cmul(make_float2( S1, -C1), v[7]);
    v[9]  = cmul(make_float2(  R,  -R), v[9]);
    v[10] = make_float2(v[10].y, -v[10].x);
    v[11] = cmul(make_float2( -R,  -R), v[11]);
    v[13] = cmul(make_float2( S1, -C1), v[13]);
    v[14] = cmul(make_float2( -R,  -R), v[14]);
    v[15] = cmul(make_float2(-C1,  S1), v[15]);
    #pragma unroll
    for (int k1 = 0; k1 < 4; k1++) dft4(v[4 * k1], v[4 * k1 + 1], v[4 * k1 + 2], v[4 * k1 + 3]);
}

// ---------------- 4096-pt radix-16 Stockham (forward, e^{-i}), 3 stages -----
__device__ float2* fft4096_r16(float2* A, float2* B) {
    float2* src = A;
    float2* dst = B;
    int ls = 0;
    #pragma unroll
    for (int stage = 0; stage < 3; stage++) {
        int m = 256 >> (4 * stage);
        int idx = threadIdx.x;
        int q = idx & ((1 << ls) - 1);
        int p = idx >> ls;
        float2 v[16];
        #pragma unroll
        for (int j = 0; j < 16; j++)
            v[j] = src[IX(q + ((p + j * m) << ls))];
        dft16(v);
        int twb = p << ls;
        #pragma unroll
        for (int j = 0; j < 16; j++) {
            float2 y = v[4 * (j & 3) + (j >> 2)];
            float2 w = g_wfft[j * twb];
            dst[IX(q + ((16 * p + j) << ls))] = cmul(w, y);
        }
        __syncthreads();
        float2* t = src; src = dst; dst = t;
        ls += 4;
    }
    return src;
}

// ---------------- forward rfft: xT[b,c,s] -> X planar bf16x2 [b*CH+c][k] ----
__global__ void __launch_bounds__(256, 3) fwd_fft_kernel() {
    extern __shared__ char smraw[];
    float2* A = (float2*)smraw;
    float2* B = A + FFT_BUF;
    int row = blockIdx.x;
    const float2* xr = (const float2*)(g_xT + (size_t)row * SEQ);
    for (int j = threadIdx.x; j < 4096; j += 256) {
        A[IX(j)] = xr[j];
    }
    __syncthreads();
    float2* R = fft4096_r16(A, B);
    __nv_bfloat162* X = g_X + (size_t)row * MODES;
    for (int k = threadIdx.x; k <= 4096; k += 256) {
        float2 Zk = R[IX(k & 4095)];
        float2 Zc = R[IX((4096 - k) & 4095)];
        float Ex = 0.5f * (Zk.x + Zc.x), Ey = 0.5f * (Zk.y - Zc.y);
        float Ox = 0.5f * (Zk.x - Zc.x), Oy = 0.5f * (Zk.y + Zc.y);
        float2 w = g_wr[k];
        float re = Ex + w.x * Oy - w.y * Ox;
        float im = Ey - w.x * Ox - w.y * Oy;
        X[k] = __floats2bfloat162_rn(FWD_SCALE * re, FWD_SCALE * im);
    }
}

// ============== tensor-core block-diagonal complex 2-layer MLP ==============
// CTA = (mode-tile of 256, block n, batch b). 512 threads; 16 warps x 16 modes.
// Weights stored in per-lane mma-fragment order: 16B/lane [wr0,wr1,wi0,wi1],
// one LDS.128 per (k,nt); -wi via bf16x2 sign XOR (exact).
// x tile row stride 104 bf16 (52 words): g*20+t mod 32 is a permutation ->
// conflict-free fragment loads and writeback.
#define MT    256
#define MLP_THREADS 512
#define XPAD  104
#define RS    52                             // XPAD/2 words
#define WFRAG_HALF  18432                    // bf16 elems per layer: 6*12*32*8
#define SW_OFF   0                           // 2 layers * 18432 * 2B = 73728 B
#define SXR_OFF  (2 * WFRAG_HALF * 2)        // 73728 B
#define SXI_OFF  (SXR_OFF + MT * XPAD * 2)   // +53248
#define SB_OFF   (SXI_OFF + MT * XPAD * 2)   // +53248
#define MLP_SMEM (SB_OFF + 4 * 96 * 4)       // +1536 = 181760 B

__device__ __forceinline__ void mma_bf16(float* c, const uint32_t* a, uint32_t b0, uint32_t b1) {
    asm volatile(
        "mma.sync.aligned.m16n8k16.row.col.f32.bf16.bf16.f32 "
        "{%0,%1,%2,%3}, {%4,%5,%6,%7}, {%8,%9}, {%0,%1,%2,%3};"
        : "+f"(c[0]), "+f"(c[1]), "+f"(c[2]), "+f"(c[3])
        : "r"(a[0]), "r"(a[1]), "r"(a[2]), "r"(a[3]), "r"(b0), "r"(b1));
}

__global__ void __launch_bounds__(MLP_THREADS) mlp_mma_kernel(const float* __restrict__ w1,
                                                              const float* __restrict__ b1,
                                                              const float* __restrict__ w2,
                                                              const float* __restrict__ b2) {
    extern __shared__ char sm[];
    __nv_bfloat16* s_wf = (__nv_bfloat16*)(sm + SW_OFF);   // [2][6][12][32][8] fragment order
    __nv_bfloat16* s_xr = (__nv_bfloat16*)(sm + SXR_OFF);  // [MT][XPAD]
    __nv_bfloat16* s_xi = (__nv_bfloat16*)(sm + SXI_OFF);
    float*         s_bv = (float*)(sm + SB_OFF);           // [4][96]

    const int tid = threadIdx.x;
    const int n   = blockIdx.y;
    const int b   = blockIdx.z;
    const int m0  = blockIdx.x * MT;

    // ---- weights -> fragment-packed smem ----
    const float* g_w1r = w1 + n * 9216;
    const float* g_w1i = w1 + 73728 + n * 9216;
    const float* g_w2r = w2 + n * 9216;
    const float* g_w2i = w2 + 73728 + n * 9216;
    for (int i = tid; i < 9216; i += MLP_THREADS) {
        int d = i / 96, kout = i % 96;       // gmem w[d][kout]
        int k  = d >> 4;                     // k-iter 0..5
        int r  = d & 15;
        int half = r >> 3;                   // word 0/1 within wr pair
        int t2   = (r & 7) >> 1;             // lane t of the lane that needs it
        int e    = r & 1;                    // bf16 within word
        int nt = kout >> 3, gg = kout & 7;
        int base = (((k * 12 + nt) * 32 + gg * 4 + t2) << 3) + half * 2 + e;
        s_wf[base]                  = __float2bfloat16_rn(g_w1r[i]);
        s_wf[base + 4]              = __float2bfloat16_rn(g_w1i[i]);
        s_wf[WFRAG_HALF + base]     = __float2bfloat16_rn(g_w2r[i]);
        s_wf[WFRAG_HALF + base + 4] = __float2bfloat16_rn(g_w2i[i]);
    }
    if (tid < 96) {
        s_bv[tid]       = b1[n * 96 + tid];
        s_bv[96 + tid]  = b1[768 + n * 96 + tid];
        s_bv[192 + tid] = b2[n * 96 + tid];
        s_bv[288 + tid] = b2[768 + n * 96 + tid];
    }

    size_t rowbase = ((size_t)b * CH + n * 96) * (size_t)MODES;
    for (int i = tid; i < 96 * MT; i += MLP_THREADS) {
        int d = i >> 8, mm = i & (MT - 1);
        int mode = m0 + mm;
        __nv_bfloat162 xv = (mode < MODES) ? g_X[rowbase + (size_t)d * MODES + mode]
                                           : __nv_bfloat162{__float2bfloat16_rn(0.f), __float2bfloat16_rn(0.f)};
        s_xr[mm * XPAD + d] = xv.x;
        s_xi[mm * XPAD + d] = xv.y;
    }
    __syncthreads();

    const int lane = tid & 31;
    const int warp = tid >> 5;           // 0..15
    const int g  = lane >> 2;
    const int t  = lane & 3;
    const int mrow = warp * 16;          // each warp owns 16 modes

    const uint4*    Wf = (const uint4*)s_wf;
    const uint32_t* Xr = (const uint32_t*)s_xr;
    const uint32_t* Xi = (const uint32_t*)s_xi;
    const uint32_t SGN = 0x80008000u;

    float cr[12][4], ci[12][4];

    // ---------- layer 1: o_r = xr*wr + (-xi)*wi ; o_i = xi*wr + xr*wi ------
    #pragma unroll
    for (int nt = 0; nt < 12; nt++) {
        float br0 = s_bv[nt * 8 + 2 * t], br1 = s_bv[nt * 8 + 2 * t + 1];
        float bi0 = s_bv[96 + nt * 8 + 2 * t], bi1 = s_bv[96 + nt * 8 + 2 * t + 1];
        cr[nt][0] = br0; cr[nt][1] = br1; cr[nt][2] = br0; cr[nt][3] = br1;
        ci[nt][0] = bi0; ci[nt][1] = bi1; ci[nt][2] = bi0; ci[nt][3] = bi1;
    }
    #pragma unroll
    for (int k = 0; k < 6; k++) {
        int kw = k * 8 + t;
        uint32_t ar[4], ai[4], nai[4];
        ar[0] = Xr[(mrow + g) * RS + kw];     ar[1] = Xr[(mrow + g + 8) * RS + kw];
        ar[2] = Xr[(mrow + g) * RS + kw + 4]; ar[3] = Xr[(mrow + g + 8) * RS + kw + 4];
        ai[0] = Xi[(mrow + g) * RS + kw];     ai[1] = Xi[(mrow + g + 8) * RS + kw];
        ai[2] = Xi[(mrow + g) * RS + kw + 4]; ai[3] = Xi[(mrow + g + 8) * RS + kw + 4];
        #pragma unroll
        for (int j = 0; j < 4; j++) nai[j] = ai[j] ^ SGN;
        #pragma unroll
        for (int nt = 0; nt < 12; nt++) {
            uint4 wv = Wf[(k * 12 + nt) * 32 + lane];
            mma_bf16(cr[nt], ar,  wv.x, wv.y);
            mma_bf16(cr[nt], nai, wv.z, wv.w);
            mma_bf16(ci[nt], ai,  wv.x, wv.y);
            mma_bf16(ci[nt], ar,  wv.z, wv.w);
        }
    }
    __syncwarp();
    {
        uint32_t* Xrw = (uint32_t*)s_xr;
        uint32_t* Xiw = (uint32_t*)s_xi;
        #pragma unroll
        for (int nt = 0; nt < 12; nt++) {
            int cw = nt * 4 + t;
            __nv_bfloat162 hh;
            hh = __floats2bfloat162_rn(fmaxf(cr[nt][0], 0.0f), fmaxf(cr[nt][1], 0.0f));
            Xrw[(mrow + g) * RS + cw] = *(uint32_t*)&hh;
            hh = __floats2bfloat162_rn(fmaxf(cr[nt][2], 0.0f), fmaxf(cr[nt][3], 0.0f));
            Xrw[(mrow + g + 8) * RS + cw] = *(uint32_t*)&hh;
            hh = __floats2bfloat162_rn(fmaxf(ci[nt][0], 0.0f), fmaxf(ci[nt][1], 0.0f));
            Xiw[(mrow + g) * RS + cw] = *(uint32_t*)&hh;
            hh = __floats2bfloat162_rn(fmaxf(ci[nt][2], 0.0f), fmaxf(ci[nt][3], 0.0f));
            Xiw[(mrow + g + 8) * RS + cw] = *(uint32_t*)&hh;
        }
    }
    __syncwarp();

    // ---------- layer 2 ----------
    #pragma unroll
    for (int nt = 0; nt < 12; nt++) {
        float br0 = s_bv[192 + nt * 8 + 2 * t], br1 = s_bv[192 + nt * 8 + 2 * t + 1];
        float bi0 = s_bv[288 + nt * 8 + 2 * t], bi1 = s_bv[288 + nt * 8 + 2 * t + 1];
        cr[nt][0] = br0; cr[nt][1] = br1; cr[nt][2] = br0; cr[nt][3] = br1;
        ci[nt][0] = bi0; ci[nt][1] = bi1; ci[nt][2] = bi0; ci[nt][3] = bi1;
    }
    #pragma unroll
    for (int k = 0; k < 6; k++) {
        int kw = k * 8 + t;
        uint32_t ar[4], ai[4], nai[4];
        ar[0] = Xr[(mrow + g) * RS + kw];     ar[1] = Xr[(mrow + g + 8) * RS + kw];
        ar[2] = Xr[(mrow + g) * RS + kw + 4]; ar[3] = Xr[(mrow + g + 8) * RS + kw + 4];
        ai[0] = Xi[(mrow + g) * RS + kw];     ai[1] = Xi[(mrow + g + 8) * RS + kw];
        ai[2] = Xi[(mrow + g) * RS + kw + 4]; ai[3] = Xi[(mrow + g + 8) * RS + kw + 4];
        #pragma unroll
        for (int j = 0; j < 4; j++) nai[j] = ai[j] ^ SGN;
        #pragma unroll
        for (int nt = 0; nt < 12; nt++) {
            uint4 wv = Wf[(72 + k * 12 + nt) * 32 + lane];   // layer 2 half (uint4 idx 2304+)
            mma_bf16(cr[nt], ar,  wv.x, wv.y);
            mma_bf16(cr[nt], nai, wv.z, wv.w);
            mma_bf16(ci[nt], ai,  wv.x, wv.y);
            mma_bf16(ci[nt], ar,  wv.z, wv.w);
        }
    }

    // ---------- softshrink + store (bf16x2) ----------
    int mode_lo = m0 + mrow + g;
    int mode_hi = mode_lo + 8;
    #pragma unroll
    for (int nt = 0; nt < 12; nt++) {
        #pragma unroll
        for (int j = 0; j < 4; j++) {
            int col  = nt * 8 + 2 * t + (j & 1);
            int mode = (j < 2) ? mode_lo : mode_hi;
            if (mode < MODES) {
                size_t off = rowbase + (size_t)col * MODES + mode;
                float vr = cr[nt][j];
                float vi = ci[nt][j];
                vr = copysignf(fmaxf(fabsf(vr) - LAM, 0.0f), vr);
                vi = copysignf(fmaxf(fabsf(vi) - LAM, 0.0f), vi);
                g_X[off] = __floats2bfloat162_rn(vr, vi);
            }
        }
    }
}

// ---------------- inverse rfft: X planar bf16x2 -> yT bf16 [b*CH+c][s] ------
__global__ void __launch_bounds__(256, 3) inv_fft_kernel() {
    extern __shared__ char smraw[];
    float2* A = (float2*)smraw;
    float2* B = A + FFT_BUF;
    int row = blockIdx.x;
    const __nv_bfloat162* X = g_X + (size_t)row * MODES;
    for (int k = threadIdx.x; k < 4096; k += 256) {
        __nv_bfloat162 xk = X[k];
        __nv_bfloat162 xc = X[4096 - k];
        float xkr = __bfloat162float(xk.x), xki = __bfloat162float(xk.y);
        float xcr = __bfloat162float(xc.x), xci = __bfloat162float(xc.y);
        if (k == 0) { xki = 0.0f; xci = 0.0f; }
        float Ex = 0.5f * (xkr + xcr), Ey = 0.5f * (xki - xci);
        float Gx = 0.5f * (xkr - xcr), Gy = 0.5f * (xki + xci);
        float2 w = g_wr[k];
        float WOx = w.x * Gx - w.y * Gy;
        float WOy = w.x * Gy + w.y * Gx;
        float Zx = Ex - WOy;
        float Zy = Ey + WOx;
        A[IX(k)] = make_float2(INV_SCALE * Zx, -INV_SCALE * Zy);
    }
    __syncthreads();
    float2* R = fft4096_r16(A, B);
    __nv_bfloat162* out = (__nv_bfloat162*)(g_yT + (size_t)row * SEQ);
    for (int j = threadIdx.x; j < 4096; j += 256) {
        float2 r = R[IX(j)];
        out[j] = __floats2bfloat162_rn(r.x, -r.y);
    }
}

// ---------------- transpose + bias: out[b,s,c] = x[b,s,c] + yT[b,c,s] -------
__global__ void __launch_bounds__(256) final_kernel(const float* __restrict__ x,
                                                    float* __restrict__ out) {
    __shared__ float t[32][33];
    int b  = blockIdx.z;
    int c0 = blockIdx.x * 32;
    int s0 = blockIdx.y * 32;
    int tx = threadIdx.x, ty = threadIdx.y;
    #pragma unroll
    for (int i = 0; i < 4; i++) {
        int cc = c0 + ty + 8 * i;
        t[ty + 8 * i][tx] = __bfloat162float(g_yT[((size_t)b * CH + cc) * SEQ + s0 + tx]);
    }
    __syncthreads();
    #pragma unroll
    for (int i = 0; i < 4; i++) {
        int s = s0 + ty + 8 * i;
        size_t off = ((size_t)b * SEQ + s) * CH + c0 + tx;
        out[off] = x[off] + t[tx][ty + 8 * i];
    }
}

// ---------------- launcher ----------------
extern "C" void kernel_launch(void* const* d_in, const int* in_sizes, int n_in,
                              void* d_out, int out_size) {
    const float* x  = (const float*)d_in[0];
    const float* w1 = (const float*)d_in[1];
    const float* b1 = (const float*)d_in[2];
    const float* w2 = (const float*)d_in[3];
    const float* b2 = (const float*)d_in[4];
    float* out = (float*)d_out;

    cudaFuncSetAttribute(fwd_fft_kernel, cudaFuncAttributeMaxDynamicSharedMemorySize, FFT_SMEM);
    cudaFuncSetAttribute(inv_fft_kernel, cudaFuncAttributeMaxDynamicSharedMemorySize, FFT_SMEM);
    cudaFuncSetAttribute(mlp_mma_kernel, cudaFuncAttributeMaxDynamicSharedMemorySize, MLP_SMEM);

    init_tables_kernel<<<17, 256>>>();
    transpose_x_kernel<<<dim3(CH / 32, SEQ / 32, BATCH), dim3(32, 8)>>>(x);
    fwd_fft_kernel<<<BATCH * CH, 256, FFT_SMEM>>>();
    mlp_mma_kernel<<<dim3((MODES + MT - 1) / MT, NBLK, BATCH), MLP_THREADS, MLP_SMEM>>>(w1, b1, w2, b2);
    inv_fft_kernel<<<BATCH * CH, 256, FFT_SMEM>>>();
    final_kernel<<<dim3(CH / 32, SEQ / 32, BATCH), dim3(32, 8)>>>(x, out);
}

// round 12
// speedup vs baseline: 1.6318x; 1.0917x over previous
#include <cuda_runtime.h>
#include <cuda_bf16.h>
#include <math.h>
#include <stdint.h>

#define BATCH 4
#define SEQ   8192
#define CH    768
#define N2    4096
#define MODES 4097
#define NBLK  8
#define LAM   0.01f

#define FWD_SCALE 0.011048543456039806f   // 1/sqrt(8192)
#define INV_SCALE 0.022097086912079613f   // sqrt(8192)/4096

// padded smem indexing: 1 extra float2 per 32 -> kills 128B-stride conflicts
#define IX(i) ((i) + ((i) >> 5))
#define FFT_BUF 4224
#define FFT_SMEM (FFT_BUF * 8)            // 33792 bytes (single in-place buffer)

#define WFRAG_HALF 18432                  // bf16 elems per layer: 6*12*32*8
#define WFRAG_N    (2 * WFRAG_HALF)       // per block n

// ---------------- device scratch ----------------
__device__ float          g_xT[BATCH * CH * SEQ];        // x transposed [b][c][s], fp32
__device__ __nv_bfloat162 g_X [BATCH * CH * MODES];      // spectrum (re,im) bf16x2
__device__ __nv_bfloat16  g_yT[BATCH * CH * SEQ];        // irfft out [b][c][s]
__device__ __nv_bfloat16  g_wfrag[NBLK * WFRAG_N];       // fragment-packed weights
__device__ float2 g_wfft[N2];     // exp(-2*pi*i*t/4096)
__device__ float2 g_wr  [MODES];  // (cos,sin)(2*pi*k/8192)

// ---------------- tables ----------------
__global__ void init_tables_kernel() {
    int i = blockIdx.x * blockDim.x + threadIdx.x;
    if (i < N2) {
        float s, c;
        sincospif((float)i * (1.0f / 2048.0f), &s, &c);
        g_wfft[i] = make_float2(c, -s);
    }
    if (i < MODES) {
        float s, c;
        sincospif((float)i * (1.0f / 4096.0f), &s, &c);
        g_wr[i] = make_float2(c, s);
    }
}

// ---------------- one-shot weight fragment packing ----------------
// Fragment order: [2 layers][6 k][12 nt][32 lanes][8 bf16: wr0 wr1 wi0 wi1]
__global__ void __launch_bounds__(512) pack_w_kernel(const float* __restrict__ w1,
                                                     const float* __restrict__ w2) {
    int n = blockIdx.x;
    const float* g_w1r = w1 + n * 9216;
    const float* g_w1i = w1 + 73728 + n * 9216;
    const float* g_w2r = w2 + n * 9216;
    const float* g_w2i = w2 + 73728 + n * 9216;
    __nv_bfloat16* dst = g_wfrag + n * WFRAG_N;
    for (int i = threadIdx.x; i < 9216; i += 512) {
        int d = i / 96, kout = i % 96;       // gmem w[d][kout]
        int k  = d >> 4;                     // k-iter 0..5
        int r  = d & 15;
        int half = r >> 3;
        int t2   = (r & 7) >> 1;
        int e    = r & 1;
        int nt = kout >> 3, gg = kout & 7;
        int base = (((k * 12 + nt) * 32 + gg * 4 + t2) << 3) + half * 2 + e;
        dst[base]                  = __float2bfloat16_rn(g_w1r[i]);
        dst[base + 4]              = __float2bfloat16_rn(g_w1i[i]);
        dst[WFRAG_HALF + base]     = __float2bfloat16_rn(g_w2r[i]);
        dst[WFRAG_HALF + base + 4] = __float2bfloat16_rn(g_w2i[i]);
    }
}

// ---------------- transpose x: [b,s,c] -> xT [b,c,s] (fp32) ----------------
__global__ void __launch_bounds__(256) transpose_x_kernel(const float* __restrict__ x) {
    __shared__ float t[32][33];
    int b  = blockIdx.z;
    int c0 = blockIdx.x * 32;
    int s0 = blockIdx.y * 32;
    int tx = threadIdx.x, ty = threadIdx.y;
    #pragma unroll
    for (int i = 0; i < 4; i++) {
        int s = s0 + ty + 8 * i;
        t[ty + 8 * i][tx] = x[((size_t)b * SEQ + s) * CH + c0 + tx];
    }
    __syncthreads();
    #pragma unroll
    for (int i = 0; i < 4; i++) {
        int cc = c0 + ty + 8 * i;
        g_xT[((size_t)b * CH + cc) * SEQ + s0 + tx] = t[tx][ty + 8 * i];
    }
}

// ---------------- complex helpers ----------------
__device__ __forceinline__ float2 cadd(float2 a, float2 b) { return make_float2(a.x + b.x, a.y + b.y); }
__device__ __forceinline__ float2 csub(float2 a, float2 b) { return make_float2(a.x - b.x, a.y - b.y); }
__device__ __forceinline__ float2 cmul(float2 a, float2 b) {
    return make_float2(fmaf(a.x, b.x, -a.y * b.y), fmaf(a.x, b.y, a.y * b.x));
}

// forward DFT4 (e^{-i}), in place
__device__ __forceinline__ void dft4(float2& a0, float2& a1, float2& a2, float2& a3) {
    float2 t0 = cadd(a0, a2), t1 = csub(a0, a2);
    float2 t2 = cadd(a1, a3), t3 = csub(a1, a3);
    a0 = cadd(t0, t2);
    a2 = csub(t0, t2);
    a1 = make_float2(t1.x + t3.y, t1.y - t3.x);
    a3 = make_float2(t1.x - t3.y, t1.y + t3.x);
}

// 16-pt DFT in registers; output X[j] lands in v[4*(j&3) + (j>>2)]
__device__ __forceinline__ void dft16(float2 v[16]) {
    #pragma unroll
    for (int i = 0; i < 4; i++) dft4(v[i], v[i + 4], v[i + 8], v[i + 12]);
    const float C1 = 0.92387953251128674f, S1 = 0.38268343236508978f, R = 0.70710678118654752f;
    v[5]  = cmul(make_float2( C1, -S1), v[5]);
    v[6]  = cmul(make_float2(  R,  -R), v[6]);
    v[7]  = cmul(make_float2( S1, -C1), v[7]);
    v[9]  = cmul(make_float2(  R,  -R), v[9]);
    v[10] = make_float2(v[10].y, -v[10].x);
    v[11] = cmul(make_float2( -R,  -R), v[11]);
    v[13] = cmul(make_float2( S1, -C1), v[13]);
    v[14] = cmul(make_float2( -R,  -R), v[14]);
    v[15] = cmul(make_float2(-C1,  S1), v[15]);
    #pragma unroll
    for (int k1 = 0; k1 < 4; k1++) dft4(v[4 * k1], v[4 * k1 + 1], v[4 * k1 + 2], v[4 * k1 + 3]);
}

// ------ 4096-pt radix-16 Stockham, IN-PLACE single buffer, 3 stages --------
// Each stage: all threads load 16 pts to regs, sync, butterfly+twiddle, store, sync.
__device__ void fft4096_ip(float2* A) {
    int ls = 0;
    #pragma unroll
    for (int stage = 0; stage < 3; stage++) {
        int m = 256 >> (4 * stage);
        int q = threadIdx.x & ((1 << ls) - 1);
        int p = threadIdx.x >> ls;
        float2 v[16];
        #pragma unroll
        for (int j = 0; j < 16; j++)
            v[j] = A[IX(q + ((p + j * m) << ls))];
        __syncthreads();
        dft16(v);
        int twb = p << ls;
        #pragma unroll
        for (int j = 0; j < 16; j++) {
            float2 y = v[4 * (j & 3) + (j >> 2)];
            float2 w = g_wfft[j * twb];
            A[IX(q + ((16 * p + j) << ls))] = cmul(w, y);
        }
        __syncthreads();
        ls += 4;
    }
}

// ---------------- forward rfft: xT[b,c,s] -> X planar bf16x2 [b*CH+c][k] ----
__global__ void __launch_bounds__(256, 4) fwd_fft_kernel() {
    extern __shared__ char smraw[];
    float2* A = (float2*)smraw;
    int row = blockIdx.x;
    const float2* xr = (const float2*)(g_xT + (size_t)row * SEQ);
    for (int j = threadIdx.x; j < 4096; j += 256) {
        A[IX(j)] = xr[j];
    }
    __syncthreads();
    fft4096_ip(A);
    __nv_bfloat162* X = g_X + (size_t)row * MODES;
    for (int k = threadIdx.x; k <= 4096; k += 256) {
        float2 Zk = A[IX(k & 4095)];
        float2 Zc = A[IX((4096 - k) & 4095)];
        float Ex = 0.5f * (Zk.x + Zc.x), Ey = 0.5f * (Zk.y - Zc.y);
        float Ox = 0.5f * (Zk.x - Zc.x), Oy = 0.5f * (Zk.y + Zc.y);
        float2 w = g_wr[k];
        float re = Ex + w.x * Oy - w.y * Ox;
        float im = Ey - w.x * Ox - w.y * Oy;
        X[k] = __floats2bfloat162_rn(FWD_SCALE * re, FWD_SCALE * im);
    }
}

// ============== tensor-core block-diagonal complex 2-layer MLP ==============
// CTA = (mode-tile of 256, block n, batch b). 512 threads; 16 warps x 16 modes.
// Weights pre-packed in gmem fragment order; prologue = plain uint4 copy.
#define MT    256
#define MLP_THREADS 512
#define XPAD  104
#define RS    52                             // XPAD/2 words
#define SW_OFF   0                           // 73728 B fragments
#define SXR_OFF  (2 * WFRAG_HALF * 2)        // 73728 B
#define SXI_OFF  (SXR_OFF + MT * XPAD * 2)   // +53248
#define SB_OFF   (SXI_OFF + MT * XPAD * 2)   // +53248
#define MLP_SMEM (SB_OFF + 4 * 96 * 4)       // +1536 = 181760 B

__device__ __forceinline__ void mma_bf16(float* c, const uint32_t* a, uint32_t b0, uint32_t b1) {
    asm volatile(
        "mma.sync.aligned.m16n8k16.row.col.f32.bf16.bf16.f32 "
        "{%0,%1,%2,%3}, {%4,%5,%6,%7}, {%8,%9}, {%0,%1,%2,%3};"
        : "+f"(c[0]), "+f"(c[1]), "+f"(c[2]), "+f"(c[3])
        : "r"(a[0]), "r"(a[1]), "r"(a[2]), "r"(a[3]), "r"(b0), "r"(b1));
}

__global__ void __launch_bounds__(MLP_THREADS) mlp_mma_kernel(const float* __restrict__ b1,
                                                              const float* __restrict__ b2) {
    extern __shared__ char sm[];
    __nv_bfloat16* s_wf = (__nv_bfloat16*)(sm + SW_OFF);   // fragment order
    __nv_bfloat16* s_xr = (__nv_bfloat16*)(sm + SXR_OFF);  // [MT][XPAD]
    __nv_bfloat16* s_xi = (__nv_bfloat16*)(sm + SXI_OFF);
    float*         s_bv = (float*)(sm + SB_OFF);           // [4][96]

    const int tid = threadIdx.x;
    const int n   = blockIdx.y;
    const int b   = blockIdx.z;
    const int m0  = blockIdx.x * MT;

    // ---- weights: straight vector copy of pre-packed fragments ----
    {
        const uint4* src = (const uint4*)(g_wfrag + (size_t)n * WFRAG_N);
        uint4* dst = (uint4*)s_wf;
        #pragma unroll
        for (int i = tid; i < WFRAG_N / 8; i += MLP_THREADS)   // 4608 uint4
            dst[i] = src[i];
    }
    if (tid < 96) {
        s_bv[tid]       = b1[n * 96 + tid];
        s_bv[96 + tid]  = b1[768 + n * 96 + tid];
        s_bv[192 + tid] = b2[n * 96 + tid];
        s_bv[288 + tid] = b2[768 + n * 96 + tid];
    }

    size_t rowbase = ((size_t)b * CH + n * 96) * (size_t)MODES;
    for (int i = tid; i < 96 * MT; i += MLP_THREADS) {
        int d = i >> 8, mm = i & (MT - 1);
        int mode = m0 + mm;
        __nv_bfloat162 xv = (mode < MODES) ? g_X[rowbase + (size_t)d * MODES + mode]
                                           : __nv_bfloat162{__float2bfloat16_rn(0.f), __float2bfloat16_rn(0.f)};
        s_xr[mm * XPAD + d] = xv.x;
        s_xi[mm * XPAD + d] = xv.y;
    }
    __syncthreads();

    const int lane = tid & 31;
    const int warp = tid >> 5;           // 0..15
    const int g  = lane >> 2;
    const int t  = lane & 3;
    const int mrow = warp * 16;          // each warp owns 16 modes

    const uint4*    Wf = (const uint4*)s_wf;
    const uint32_t* Xr = (const uint32_t*)s_xr;
    const uint32_t* Xi = (const uint32_t*)s_xi;
    const uint32_t SGN = 0x80008000u;

    float cr[12][4], ci[12][4];

    // ---------- layer 1: o_r = xr*wr + (-xi)*wi ; o_i = xi*wr + xr*wi ------
    #pragma unroll
    for (int nt = 0; nt < 12; nt++) {
        float br0 = s_bv[nt * 8 + 2 * t], br1 = s_bv[nt * 8 + 2 * t + 1];
        float bi0 = s_bv[96 + nt * 8 + 2 * t], bi1 = s_bv[96 + nt * 8 + 2 * t + 1];
        cr[nt][0] = br0; cr[nt][1] = br1; cr[nt][2] = br0; cr[nt][3] = br1;
        ci[nt][0] = bi0; ci[nt][1] = bi1; ci[nt][2] = bi0; ci[nt][3] = bi1;
    }
    #pragma unroll
    for (int k = 0; k < 6; k++) {
        int kw = k * 8 + t;
        uint32_t ar[4], ai[4], nai[4];
        ar[0] = Xr[(mrow + g) * RS + kw];     ar[1] = Xr[(mrow + g + 8) * RS + kw];
        ar[2] = Xr[(mrow + g) * RS + kw + 4]; ar[3] = Xr[(mrow + g + 8) * RS + kw + 4];
        ai[0] = Xi[(mrow + g) * RS + kw];     ai[1] = Xi[(mrow + g + 8) * RS + kw];
        ai[2] = Xi[(mrow + g) * RS + kw + 4]; ai[3] = Xi[(mrow + g + 8) * RS + kw + 4];
        #pragma unroll
        for (int j = 0; j < 4; j++) nai[j] = ai[j] ^ SGN;
        #pragma unroll
        for (int nt = 0; nt < 12; nt++) {
            uint4 wv = Wf[(k * 12 + nt) * 32 + lane];
            mma_bf16(cr[nt], ar,  wv.x, wv.y);
            mma_bf16(cr[nt], nai, wv.z, wv.w);
            mma_bf16(ci[nt], ai,  wv.x, wv.y);
            mma_bf16(ci[nt], ar,  wv.z, wv.w);
        }
    }
    __syncwarp();
    {
        uint32_t* Xrw = (uint32_t*)s_xr;
        uint32_t* Xiw = (uint32_t*)s_xi;
        #pragma unroll
        for (int nt = 0; nt < 12; nt++) {
            int cw = nt * 4 + t;
            __nv_bfloat162 hh;
            hh = __floats2bfloat162_rn(fmaxf(cr[nt][0], 0.0f), fmaxf(cr[nt][1], 0.0f));
            Xrw[(mrow + g) * RS + cw] = *(uint32_t*)&hh;
            hh = __floats2bfloat162_rn(fmaxf(cr[nt][2], 0.0f), fmaxf(cr[nt][3], 0.0f));
            Xrw[(mrow + g + 8) * RS + cw] = *(uint32_t*)&hh;
            hh = __floats2bfloat162_rn(fmaxf(ci[nt][0], 0.0f), fmaxf(ci[nt][1], 0.0f));
            Xiw[(mrow + g) * RS + cw] = *(uint32_t*)&hh;
            hh = __floats2bfloat162_rn(fmaxf(ci[nt][2], 0.0f), fmaxf(ci[nt][3], 0.0f));
            Xiw[(mrow + g + 8) * RS + cw] = *(uint32_t*)&hh;
        }
    }
    __syncwarp();

    // ---------- layer 2 ----------
    #pragma unroll
    for (int nt = 0; nt < 12; nt++) {
        float br0 = s_bv[192 + nt * 8 + 2 * t], br1 = s_bv[192 + nt * 8 + 2 * t + 1];
        float bi0 = s_bv[288 + nt * 8 + 2 * t], bi1 = s_bv[288 + nt * 8 + 2 * t + 1];
        cr[nt][0] = br0; cr[nt][1] = br1; cr[nt][2] = br0; cr[nt][3] = br1;
        ci[nt][0] = bi0; ci[nt][1] = bi1; ci[nt][2] = bi0; ci[nt][3] = bi1;
    }
    #pragma unroll
    for (int k = 0; k < 6; k++) {
        int kw = k * 8 + t;
        uint32_t ar[4], ai[4], nai[4];
        ar[0] = Xr[(mrow + g) * RS + kw];     ar[1] = Xr[(mrow + g + 8) * RS + kw];
        ar[2] = Xr[(mrow + g) * RS + kw + 4]; ar[3] = Xr[(mrow + g + 8) * RS + kw + 4];
        ai[0] = Xi[(mrow + g) * RS + kw];     ai[1] = Xi[(mrow + g + 8) * RS + kw];
        ai[2] = Xi[(mrow + g) * RS + kw + 4]; ai[3] = Xi[(mrow + g + 8) * RS + kw + 4];
        #pragma unroll
        for (int j = 0; j < 4; j++) nai[j] = ai[j] ^ SGN;
        #pragma unroll
        for (int nt = 0; nt < 12; nt++) {
            uint4 wv = Wf[(72 + k * 12 + nt) * 32 + lane];   // layer 2 half
            mma_bf16(cr[nt], ar,  wv.x, wv.y);
            mma_bf16(cr[nt], nai, wv.z, wv.w);
            mma_bf16(ci[nt], ai,  wv.x, wv.y);
            mma_bf16(ci[nt], ar,  wv.z, wv.w);
        }
    }

    // ---------- softshrink + store (bf16x2) ----------
    int mode_lo = m0 + mrow + g;
    int mode_hi = mode_lo + 8;
    #pragma unroll
    for (int nt = 0; nt < 12; nt++) {
        #pragma unroll
        for (int j = 0; j < 4; j++) {
            int col  = nt * 8 + 2 * t + (j & 1);
            int mode = (j < 2) ? mode_lo : mode_hi;
            if (mode < MODES) {
                size_t off = rowbase + (size_t)col * MODES + mode;
                float vr = cr[nt][j];
                float vi = ci[nt][j];
                vr = copysignf(fmaxf(fabsf(vr) - LAM, 0.0f), vr);
                vi = copysignf(fmaxf(fabsf(vi) - LAM, 0.0f), vi);
                g_X[off] = __floats2bfloat162_rn(vr, vi);
            }
        }
    }
}

// ---------------- inverse rfft: X planar bf16x2 -> yT bf16 [b*CH+c][s] ------
__global__ void __launch_bounds__(256, 4) inv_fft_kernel() {
    extern __shared__ char smraw[];
    float2* A = (float2*)smraw;
    int row = blockIdx.x;
    const __nv_bfloat162* X = g_X + (size_t)row * MODES;
    for (int k = threadIdx.x; k < 4096; k += 256) {
        __nv_bfloat162 xk = X[k];
        __nv_bfloat162 xc = X[4096 - k];
        float xkr = __bfloat162float(xk.x), xki = __bfloat162float(xk.y);
        float xcr = __bfloat162float(xc.x), xci = __bfloat162float(xc.y);
        if (k == 0) { xki = 0.0f; xci = 0.0f; }
        float Ex = 0.5f * (xkr + xcr), Ey = 0.5f * (xki - xci);
        float Gx = 0.5f * (xkr - xcr), Gy = 0.5f * (xki + xci);
        float2 w = g_wr[k];
        float WOx = w.x * Gx - w.y * Gy;
        float WOy = w.x * Gy + w.y * Gx;
        float Zx = Ex - WOy;
        float Zy = Ey + WOx;
        A[IX(k)] = make_float2(INV_SCALE * Zx, -INV_SCALE * Zy);
    }
    __syncthreads();
    fft4096_ip(A);
    __nv_bfloat162* out = (__nv_bfloat162*)(g_yT + (size_t)row * SEQ);
    for (int j = threadIdx.x; j < 4096; j += 256) {
        float2 r = A[IX(j)];
        out[j] = __floats2bfloat162_rn(r.x, -r.y);
    }
}

// ---------------- transpose + bias: out[b,s,c] = x[b,s,c] + yT[b,c,s] -------
__global__ void __launch_bounds__(256) final_kernel(const float* __restrict__ x,
                                                    float* __restrict__ out) {
    __shared__ float t[32][33];
    int b  = blockIdx.z;
    int c0 = blockIdx.x * 32;
    int s0 = blockIdx.y * 32;
    int tx = threadIdx.x, ty = threadIdx.y;
    #pragma unroll
    for (int i = 0; i < 4; i++) {
        int cc = c0 + ty + 8 * i;
        t[ty + 8 * i][tx] = __bfloat162float(g_yT[((size_t)b * CH + cc) * SEQ + s0 + tx]);
    }
    __syncthreads();
    #pragma unroll
    for (int i = 0; i < 4; i++) {
        int s = s0 + ty + 8 * i;
        size_t off = ((size_t)b * SEQ + s) * CH + c0 + tx;
        out[off] = x[off] + t[tx][ty + 8 * i];
    }
}

// ---------------- launcher ----------------
extern "C" void kernel_launch(void* const* d_in, const int* in_sizes, int n_in,
                              void* d_out, int out_size) {
    const float* x  = (const float*)d_in[0];
    const float* w1 = (const float*)d_in[1];
    const float* b1 = (const float*)d_in[2];
    const float* w2 = (const float*)d_in[3];
    const float* b2 = (const float*)d_in[4];
    float* out = (float*)d_out;

    cudaFuncSetAttribute(fwd_fft_kernel, cudaFuncAttributeMaxDynamicSharedMemorySize, FFT_SMEM);
    cudaFuncSetAttribute(inv_fft_kernel, cudaFuncAttributeMaxDynamicSharedMemorySize, FFT_SMEM);
    cudaFuncSetAttribute(mlp_mma_kernel, cudaFuncAttributeMaxDynamicSharedMemorySize, MLP_SMEM);

    init_tables_kernel<<<17, 256>>>();
    pack_w_kernel<<<NBLK, 512>>>(w1, w2);
    transpose_x_kernel<<<dim3(CH / 32, SEQ / 32, BATCH), dim3(32, 8)>>>(x);
    fwd_fft_kernel<<<BATCH * CH, 256, FFT_SMEM>>>();
    mlp_mma_kernel<<<dim3((MODES + MT - 1) / MT, NBLK, BATCH), MLP_THREADS, MLP_SMEM>>>(b1, b2);
    inv_fft_kernel<<<BATCH * CH, 256, FFT_SMEM>>>();
    final_kernel<<<dim3(CH / 32, SEQ / 32, BATCH), dim3(32, 8)>>>(x, out);
}

// round 13
// speedup vs baseline: 1.7363x; 1.0640x over previous
#include <cuda_runtime.h>
#include <cuda_bf16.h>
#include <math.h>
#include <stdint.h>

#define BATCH 4
#define SEQ   8192
#define CH    768
#define N2    4096
#define MODES 4097
#define NBLK  8
#define LAM   0.01f

#define FWD_SCALE 0.011048543456039806f   // 1/sqrt(8192)
#define INV_SCALE 0.022097086912079613f   // sqrt(8192)/4096

// padded smem indexing: 1 extra float2 per 32 -> kills 128B-stride conflicts
#define IX(i) ((i) + ((i) >> 5))
#define FFT_BUF 4224
#define FFT_SMEM (FFT_BUF * 8)            // 33792 bytes (single in-place buffer)

#define WFRAG_HALF 18432                  // bf16 elems per layer: 6*12*32*8
#define WFRAG_N    (2 * WFRAG_HALF)       // per block n

// ---------------- device scratch ----------------
__device__ __nv_bfloat16  g_xTb[BATCH * CH * SEQ];       // x transposed [b][c][s], bf16
__device__ __nv_bfloat162 g_X [BATCH * CH * MODES];      // spectrum (re,im) bf16x2
__device__ __nv_bfloat16  g_yT[BATCH * CH * SEQ];        // irfft out [b][c][s]
__device__ __nv_bfloat16  g_wfrag[NBLK * WFRAG_N];       // fragment-packed weights
__device__ float2 g_wfft[N2];     // exp(-2*pi*i*t/4096)
__device__ float2 g_wr  [MODES];  // (cos,sin)(2*pi*k/8192)

// ---------------- tables ----------------
__global__ void init_tables_kernel() {
    int i = blockIdx.x * blockDim.x + threadIdx.x;
    if (i < N2) {
        float s, c;
        sincospif((float)i * (1.0f / 2048.0f), &s, &c);
        g_wfft[i] = make_float2(c, -s);
    }
    if (i < MODES) {
        float s, c;
        sincospif((float)i * (1.0f / 4096.0f), &s, &c);
        g_wr[i] = make_float2(c, s);
    }
}

// ---------------- one-shot weight fragment packing ----------------
__global__ void __launch_bounds__(512) pack_w_kernel(const float* __restrict__ w1,
                                                     const float* __restrict__ w2) {
    int n = blockIdx.x;
    const float* g_w1r = w1 + n * 9216;
    const float* g_w1i = w1 + 73728 + n * 9216;
    const float* g_w2r = w2 + n * 9216;
    const float* g_w2i = w2 + 73728 + n * 9216;
    __nv_bfloat16* dst = g_wfrag + n * WFRAG_N;
    for (int i = threadIdx.x; i < 9216; i += 512) {
        int d = i / 96, kout = i % 96;
        int k  = d >> 4;
        int r  = d & 15;
        int half = r >> 3;
        int t2   = (r & 7) >> 1;
        int e    = r & 1;
        int nt = kout >> 3, gg = kout & 7;
        int base = (((k * 12 + nt) * 32 + gg * 4 + t2) << 3) + half * 2 + e;
        dst[base]                  = __float2bfloat16_rn(g_w1r[i]);
        dst[base + 4]              = __float2bfloat16_rn(g_w1i[i]);
        dst[WFRAG_HALF + base]     = __float2bfloat16_rn(g_w2r[i]);
        dst[WFRAG_HALF + base + 4] = __float2bfloat16_rn(g_w2i[i]);
    }
}

// -------- transpose x: [b,s,c] fp32 -> xTb [b,c,s] bf16 (paired stores) -----
// Tile: 32 channels x 64 seq. Store phase packs (s even, s odd) into bf16x2.
__global__ void __launch_bounds__(256) transpose_x_kernel(const float* __restrict__ x) {
    __shared__ float t[64][33];
    int b  = blockIdx.z;
    int c0 = blockIdx.x * 32;
    int s0 = blockIdx.y * 64;
    int tx = threadIdx.x, ty = threadIdx.y;
    #pragma unroll
    for (int i = 0; i < 8; i++) {
        int s = s0 + ty + 8 * i;
        t[ty + 8 * i][tx] = x[((size_t)b * SEQ + s) * CH + c0 + tx];
    }
    __syncthreads();
    #pragma unroll
    for (int i = 0; i < 4; i++) {
        int cc = c0 + ty + 8 * i;
        __nv_bfloat162 v = __floats2bfloat162_rn(t[2 * tx][cc - c0], t[2 * tx + 1][cc - c0]);
        *(__nv_bfloat162*)(g_xTb + ((size_t)b * CH + cc) * SEQ + s0 + 2 * tx) = v;
    }
}

// ---------------- complex helpers ----------------
__device__ __forceinline__ float2 cadd(float2 a, float2 b) { return make_float2(a.x + b.x, a.y + b.y); }
__device__ __forceinline__ float2 csub(float2 a, float2 b) { return make_float2(a.x - b.x, a.y - b.y); }
__device__ __forceinline__ float2 cmul(float2 a, float2 b) {
    return make_float2(fmaf(a.x, b.x, -a.y * b.y), fmaf(a.x, b.y, a.y * b.x));
}

// forward DFT4 (e^{-i}), in place
__device__ __forceinline__ void dft4(float2& a0, float2& a1, float2& a2, float2& a3) {
    float2 t0 = cadd(a0, a2), t1 = csub(a0, a2);
    float2 t2 = cadd(a1, a3), t3 = csub(a1, a3);
    a0 = cadd(t0, t2);
    a2 = csub(t0, t2);
    a1 = make_float2(t1.x + t3.y, t1.y - t3.x);
    a3 = make_float2(t1.x - t3.y, t1.y + t3.x);
}

// 16-pt DFT in registers; output X[j] lands in v[4*(j&3) + (j>>2)]
__device__ __forceinline__ void dft16(float2 v[16]) {
    #pragma unroll
    for (int i = 0; i < 4; i++) dft4(v[i], v[i + 4], v[i + 8], v[i + 12]);
    const float C1 = 0.92387953251128674f, S1 = 0.38268343236508978f, R = 0.70710678118654752f;
    v[5]  = cmul(make_float2( C1, -S1), v[5]);
    v[6]  = cmul(make_float2(  R,  -R), v[6]);
    v[7]  = cmul(make_float2( S1, -C1), v[7]);
    v[9]  = cmul(make_float2(  R,  -R), v[9]);
    v[10] = make_float2(v[10].y, -v[10].x);
    v[11] = cmul(make_float2( -R,  -R), v[11]);
    v[13] = cmul(make_float2( S1, -C1), v[13]);
    v[14] = cmul(make_float2( -R,  -R), v[14]);
    v[15] = cmul(make_float2(-C1,  S1), v[15]);
    #pragma unroll
    for (int k1 = 0; k1 < 4; k1++) dft4(v[4 * k1], v[4 * k1 + 1], v[4 * k1 + 2], v[4 * k1 + 3]);
}

// ------ 4096-pt radix-16 Stockham, IN-PLACE single buffer, 3 stages --------
__device__ void fft4096_ip(float2* A) {
    int ls = 0;
    #pragma unroll
    for (int stage = 0; stage < 3; stage++) {
        int m = 256 >> (4 * stage);
        int q = threadIdx.x & ((1 << ls) - 1);
        int p = threadIdx.x >> ls;
        float2 v[16];
        #pragma unroll
        for (int j = 0; j < 16; j++)
            v[j] = A[IX(q + ((p + j * m) << ls))];
        __syncthreads();
        dft16(v);
        int twb = p << ls;
        #pragma unroll
        for (int j = 0; j < 16; j++) {
            float2 y = v[4 * (j & 3) + (j >> 2)];
            float2 w = g_wfft[j * twb];
            A[IX(q + ((16 * p + j) << ls))] = cmul(w, y);
        }
        __syncthreads();
        ls += 4;
    }
}

// ---------------- forward rfft: xTb[b,c,s] bf16 -> X planar bf16x2 ----------
__global__ void __launch_bounds__(256, 4) fwd_fft_kernel() {
    extern __shared__ char smraw[];
    float2* A = (float2*)smraw;
    int row = blockIdx.x;
    const __nv_bfloat162* xr = (const __nv_bfloat162*)(g_xTb + (size_t)row * SEQ);
    for (int j = threadIdx.x; j < 4096; j += 256) {
        __nv_bfloat162 p = xr[j];
        A[IX(j)] = make_float2(__bfloat162float(p.x), __bfloat162float(p.y));
    }
    __syncthreads();
    fft4096_ip(A);
    __nv_bfloat162* X = g_X + (size_t)row * MODES;
    for (int k = threadIdx.x; k <= 4096; k += 256) {
        float2 Zk = A[IX(k & 4095)];
        float2 Zc = A[IX((4096 - k) & 4095)];
        float Ex = 0.5f * (Zk.x + Zc.x), Ey = 0.5f * (Zk.y - Zc.y);
        float Ox = 0.5f * (Zk.x - Zc.x), Oy = 0.5f * (Zk.y + Zc.y);
        float2 w = g_wr[k];
        float re = Ex + w.x * Oy - w.y * Ox;
        float im = Ey - w.x * Ox - w.y * Oy;
        X[k] = __floats2bfloat162_rn(FWD_SCALE * re, FWD_SCALE * im);
    }
}

// ============== tensor-core block-diagonal complex 2-layer MLP ==============
#define MT    256
#define MLP_THREADS 512
#define XPAD  104
#define RS    52                             // XPAD/2 words
#define SW_OFF   0                           // 73728 B fragments
#define SXR_OFF  (2 * WFRAG_HALF * 2)        // 73728 B
#define SXI_OFF  (SXR_OFF + MT * XPAD * 2)   // +53248
#define SB_OFF   (SXI_OFF + MT * XPAD * 2)   // +53248
#define MLP_SMEM (SB_OFF + 4 * 96 * 4)       // +1536 = 181760 B

__device__ __forceinline__ void mma_bf16(float* c, const uint32_t* a, uint32_t b0, uint32_t b1) {
    asm volatile(
        "mma.sync.aligned.m16n8k16.row.col.f32.bf16.bf16.f32 "
        "{%0,%1,%2,%3}, {%4,%5,%6,%7}, {%8,%9}, {%0,%1,%2,%3};"
        : "+f"(c[0]), "+f"(c[1]), "+f"(c[2]), "+f"(c[3])
        : "r"(a[0]), "r"(a[1]), "r"(a[2]), "r"(a[3]), "r"(b0), "r"(b1));
}

__global__ void __launch_bounds__(MLP_THREADS) mlp_mma_kernel(const float* __restrict__ b1,
                                                              const float* __restrict__ b2) {
    extern __shared__ char sm[];
    __nv_bfloat16* s_wf = (__nv_bfloat16*)(sm + SW_OFF);
    __nv_bfloat16* s_xr = (__nv_bfloat16*)(sm + SXR_OFF);
    __nv_bfloat16* s_xi = (__nv_bfloat16*)(sm + SXI_OFF);
    float*         s_bv = (float*)(sm + SB_OFF);

    const int tid = threadIdx.x;
    const int n   = blockIdx.y;
    const int b   = blockIdx.z;
    const int m0  = blockIdx.x * MT;

    {
        const uint4* src = (const uint4*)(g_wfrag + (size_t)n * WFRAG_N);
        uint4* dst = (uint4*)s_wf;
        #pragma unroll
        for (int i = tid; i < WFRAG_N / 8; i += MLP_THREADS)
            dst[i] = src[i];
    }
    if (tid < 96) {
        s_bv[tid]       = b1[n * 96 + tid];
        s_bv[96 + tid]  = b1[768 + n * 96 + tid];
        s_bv[192 + tid] = b2[n * 96 + tid];
        s_bv[288 + tid] = b2[768 + n * 96 + tid];
    }

    size_t rowbase = ((size_t)b * CH + n * 96) * (size_t)MODES;
    for (int i = tid; i < 96 * MT; i += MLP_THREADS) {
        int d = i >> 8, mm = i & (MT - 1);
        int mode = m0 + mm;
        __nv_bfloat162 xv = (mode < MODES) ? g_X[rowbase + (size_t)d * MODES + mode]
                                           : __nv_bfloat162{__float2bfloat16_rn(0.f), __float2bfloat16_rn(0.f)};
        s_xr[mm * XPAD + d] = xv.x;
        s_xi[mm * XPAD + d] = xv.y;
    }
    __syncthreads();

    const int lane = tid & 31;
    const int warp = tid >> 5;
    const int g  = lane >> 2;
    const int t  = lane & 3;
    const int mrow = warp * 16;

    const uint4*    Wf = (const uint4*)s_wf;
    const uint32_t* Xr = (const uint32_t*)s_xr;
    const uint32_t* Xi = (const uint32_t*)s_xi;
    const uint32_t SGN = 0x80008000u;

    float cr[12][4], ci[12][4];

    // ---------- layer 1 ----------
    #pragma unroll
    for (int nt = 0; nt < 12; nt++) {
        float br0 = s_bv[nt * 8 + 2 * t], br1 = s_bv[nt * 8 + 2 * t + 1];
        float bi0 = s_bv[96 + nt * 8 + 2 * t], bi1 = s_bv[96 + nt * 8 + 2 * t + 1];
        cr[nt][0] = br0; cr[nt][1] = br1; cr[nt][2] = br0; cr[nt][3] = br1;
        ci[nt][0] = bi0; ci[nt][1] = bi1; ci[nt][2] = bi0; ci[nt][3] = bi1;
    }
    #pragma unroll
    for (int k = 0; k < 6; k++) {
        int kw = k * 8 + t;
        uint32_t ar[4], ai[4], nai[4];
        ar[0] = Xr[(mrow + g) * RS + kw];     ar[1] = Xr[(mrow + g + 8) * RS + kw];
        ar[2] = Xr[(mrow + g) * RS + kw + 4]; ar[3] = Xr[(mrow + g + 8) * RS + kw + 4];
        ai[0] = Xi[(mrow + g) * RS + kw];     ai[1] = Xi[(mrow + g + 8) * RS + kw];
        ai[2] = Xi[(mrow + g) * RS + kw + 4]; ai[3] = Xi[(mrow + g + 8) * RS + kw + 4];
        #pragma unroll
        for (int j = 0; j < 4; j++) nai[j] = ai[j] ^ SGN;
        #pragma unroll
        for (int nt = 0; nt < 12; nt++) {
            uint4 wv = Wf[(k * 12 + nt) * 32 + lane];
            mma_bf16(cr[nt], ar,  wv.x, wv.y);
            mma_bf16(cr[nt], nai, wv.z, wv.w);
            mma_bf16(ci[nt], ai,  wv.x, wv.y);
            mma_bf16(ci[nt], ar,  wv.z, wv.w);
        }
    }
    __syncwarp();
    {
        uint32_t* Xrw = (uint32_t*)s_xr;
        uint32_t* Xiw = (uint32_t*)s_xi;
        #pragma unroll
        for (int nt = 0; nt < 12; nt++) {
            int cw = nt * 4 + t;
            __nv_bfloat162 hh;
            hh = __floats2bfloat162_rn(fmaxf(cr[nt][0], 0.0f), fmaxf(cr[nt][1], 0.0f));
            Xrw[(mrow + g) * RS + cw] = *(uint32_t*)&hh;
            hh = __floats2bfloat162_rn(fmaxf(cr[nt][2], 0.0f), fmaxf(cr[nt][3], 0.0f));
            Xrw[(mrow + g + 8) * RS + cw] = *(uint32_t*)&hh;
            hh = __floats2bfloat162_rn(fmaxf(ci[nt][0], 0.0f), fmaxf(ci[nt][1], 0.0f));
            Xiw[(mrow + g) * RS + cw] = *(uint32_t*)&hh;
            hh = __floats2bfloat162_rn(fmaxf(ci[nt][2], 0.0f), fmaxf(ci[nt][3], 0.0f));
            Xiw[(mrow + g + 8) * RS + cw] = *(uint32_t*)&hh;
        }
    }
    __syncwarp();

    // ---------- layer 2 ----------
    #pragma unroll
    for (int nt = 0; nt < 12; nt++) {
        float br0 = s_bv[192 + nt * 8 + 2 * t], br1 = s_bv[192 + nt * 8 + 2 * t + 1];
        float bi0 = s_bv[288 + nt * 8 + 2 * t], bi1 = s_bv[288 + nt * 8 + 2 * t + 1];
        cr[nt][0] = br0; cr[nt][1] = br1; cr[nt][2] = br0; cr[nt][3] = br1;
        ci[nt][0] = bi0; ci[nt][1] = bi1; ci[nt][2] = bi0; ci[nt][3] = bi1;
    }
    #pragma unroll
    for (int k = 0; k < 6; k++) {
        int kw = k * 8 + t;
        uint32_t ar[4], ai[4], nai[4];
        ar[0] = Xr[(mrow + g) * RS + kw];     ar[1] = Xr[(mrow + g + 8) * RS + kw];
        ar[2] = Xr[(mrow + g) * RS + kw + 4]; ar[3] = Xr[(mrow + g + 8) * RS + kw + 4];
        ai[0] = Xi[(mrow + g) * RS + kw];     ai[1] = Xi[(mrow + g + 8) * RS + kw];
        ai[2] = Xi[(mrow + g) * RS + kw + 4]; ai[3] = Xi[(mrow + g + 8) * RS + kw + 4];
        #pragma unroll
        for (int j = 0; j < 4; j++) nai[j] = ai[j] ^ SGN;
        #pragma unroll
        for (int nt = 0; nt < 12; nt++) {
            uint4 wv = Wf[(72 + k * 12 + nt) * 32 + lane];
            mma_bf16(cr[nt], ar,  wv.x, wv.y);
            mma_bf16(cr[nt], nai, wv.z, wv.w);
            mma_bf16(ci[nt], ai,  wv.x, wv.y);
            mma_bf16(ci[nt], ar,  wv.z, wv.w);
        }
    }

    // ---------- softshrink + store (bf16x2) ----------
    int mode_lo = m0 + mrow + g;
    int mode_hi = mode_lo + 8;
    #pragma unroll
    for (int nt = 0; nt < 12; nt++) {
        #pragma unroll
        for (int j = 0; j < 4; j++) {
            int col  = nt * 8 + 2 * t + (j & 1);
            int mode = (j < 2) ? mode_lo : mode_hi;
            if (mode < MODES) {
                size_t off = rowbase + (size_t)col * MODES + mode;
                float vr = cr[nt][j];
                float vi = ci[nt][j];
                vr = copysignf(fmaxf(fabsf(vr) - LAM, 0.0f), vr);
                vi = copysignf(fmaxf(fabsf(vi) - LAM, 0.0f), vi);
                g_X[off] = __floats2bfloat162_rn(vr, vi);
            }
        }
    }
}

// ---------------- inverse rfft: X planar bf16x2 -> yT bf16 [b*CH+c][s] ------
__global__ void __launch_bounds__(256, 4) inv_fft_kernel() {
    extern __shared__ char smraw[];
    float2* A = (float2*)smraw;
    int row = blockIdx.x;
    const __nv_bfloat162* X = g_X + (size_t)row * MODES;
    for (int k = threadIdx.x; k < 4096; k += 256) {
        __nv_bfloat162 xk = X[k];
        __nv_bfloat162 xc = X[4096 - k];
        float xkr = __bfloat162float(xk.x), xki = __bfloat162float(xk.y);
        float xcr = __bfloat162float(xc.x), xci = __bfloat162float(xc.y);
        if (k == 0) { xki = 0.0f; xci = 0.0f; }
        float Ex = 0.5f * (xkr + xcr), Ey = 0.5f * (xki - xci);
        float Gx = 0.5f * (xkr - xcr), Gy = 0.5f * (xki + xci);
        float2 w = g_wr[k];
        float WOx = w.x * Gx - w.y * Gy;
        float WOy = w.x * Gy + w.y * Gx;
        float Zx = Ex - WOy;
        float Zy = Ey + WOx;
        A[IX(k)] = make_float2(INV_SCALE * Zx, -INV_SCALE * Zy);
    }
    __syncthreads();
    fft4096_ip(A);
    __nv_bfloat162* out = (__nv_bfloat162*)(g_yT + (size_t)row * SEQ);
    for (int j = threadIdx.x; j < 4096; j += 256) {
        float2 r = A[IX(j)];
        out[j] = __floats2bfloat162_rn(r.x, -r.y);
    }
}

// ---------------- transpose + bias: out[b,s,c] = x[b,s,c] + yT[b,c,s] -------
__global__ void __launch_bounds__(256) final_kernel(const float* __restrict__ x,
                                                    float* __restrict__ out) {
    __shared__ float t[32][33];
    int b  = blockIdx.z;
    int c0 = blockIdx.x * 32;
    int s0 = blockIdx.y * 32;
    int tx = threadIdx.x, ty = threadIdx.y;
    #pragma unroll
    for (int i = 0; i < 4; i++) {
        int cc = c0 + ty + 8 * i;
        t[ty + 8 * i][tx] = __bfloat162float(g_yT[((size_t)b * CH + cc) * SEQ + s0 + tx]);
    }
    __syncthreads();
    #pragma unroll
    for (int i = 0; i < 4; i++) {
        int s = s0 + ty + 8 * i;
        size_t off = ((size_t)b * SEQ + s) * CH + c0 + tx;
        out[off] = x[off] + t[tx][ty + 8 * i];
    }
}

// ---------------- launcher ----------------
extern "C" void kernel_launch(void* const* d_in, const int* in_sizes, int n_in,
                              void* d_out, int out_size) {
    const float* x  = (const float*)d_in[0];
    const float* w1 = (const float*)d_in[1];
    const float* b1 = (const float*)d_in[2];
    const float* w2 = (const float*)d_in[3];
    const float* b2 = (const float*)d_in[4];
    float* out = (float*)d_out;

    cudaFuncSetAttribute(fwd_fft_kernel, cudaFuncAttributeMaxDynamicSharedMemorySize, FFT_SMEM);
    cudaFuncSetAttribute(inv_fft_kernel, cudaFuncAttributeMaxDynamicSharedMemorySize, FFT_SMEM);
    cudaFuncSetAttribute(mlp_mma_kernel, cudaFuncAttributeMaxDynamicSharedMemorySize, MLP_SMEM);

    init_tables_kernel<<<17, 256>>>();
    pack_w_kernel<<<NBLK, 512>>>(w1, w2);
    transpose_x_kernel<<<dim3(CH / 32, SEQ / 64, BATCH), dim3(32, 8)>>>(x);
    fwd_fft_kernel<<<BATCH * CH, 256, FFT_SMEM>>>();
    mlp_mma_kernel<<<dim3((MODES + MT - 1) / MT, NBLK, BATCH), MLP_THREADS, MLP_SMEM>>>(b1, b2);
    inv_fft_kernel<<<BATCH * CH, 256, FFT_SMEM>>>();
    final_kernel<<<dim3(CH / 32, SEQ / 32, BATCH), dim3(32, 8)>>>(x, out);
}

// round 14
// speedup vs baseline: 2.0548x; 1.1834x over previous
#include <cuda_runtime.h>
#include <cuda_bf16.h>
#include <math.h>
#include <stdint.h>

#define BATCH 4
#define SEQ   8192
#define CH    768
#define N2    4096
#define MODES 4097
#define NBLK  8
#define LAM   0.01f

#define FWD_SCALE 0.011048543456039806f   // 1/sqrt(8192)
#define INV_SCALE 0.022097086912079613f   // sqrt(8192)/4096

// padded smem indexing: 1 extra float2 per 32 -> kills 128B-stride conflicts
#define IX(i) ((i) + ((i) >> 5))
#define FFT_BUF 4224
#define FFT_SMEM (FFT_BUF * 8)            // 33792 bytes (single in-place buffer)

#define WFRAG_HALF 18432                  // bf16 elems per layer: 6*12*32*8
#define WFRAG_N    (2 * WFRAG_HALF)       // per block n

// ---------------- device scratch ----------------
__device__ __nv_bfloat16  g_xTb[BATCH * CH * SEQ];       // x transposed [b][c][s], bf16
__device__ __nv_bfloat162 g_X [BATCH * CH * MODES];      // spectrum (re,im) bf16x2
__device__ __nv_bfloat16  g_yT[BATCH * CH * SEQ];        // irfft out [b][c][s]
__device__ __nv_bfloat16  g_wfrag[NBLK * WFRAG_N];       // fragment-packed weights
__device__ float2 g_wfft[N2];     // exp(-2*pi*i*t/4096)
__device__ float2 g_wr  [MODES];  // (cos,sin)(2*pi*k/8192)

// ---------------- tables ----------------
__global__ void init_tables_kernel() {
    int i = blockIdx.x * blockDim.x + threadIdx.x;
    if (i < N2) {
        float s, c;
        sincospif((float)i * (1.0f / 2048.0f), &s, &c);
        g_wfft[i] = make_float2(c, -s);
    }
    if (i < MODES) {
        float s, c;
        sincospif((float)i * (1.0f / 4096.0f), &s, &c);
        g_wr[i] = make_float2(c, s);
    }
}

// ---------------- one-shot weight fragment packing ----------------
__global__ void __launch_bounds__(512) pack_w_kernel(const float* __restrict__ w1,
                                                     const float* __restrict__ w2) {
    int n = blockIdx.x;
    const float* g_w1r = w1 + n * 9216;
    const float* g_w1i = w1 + 73728 + n * 9216;
    const float* g_w2r = w2 + n * 9216;
    const float* g_w2i = w2 + 73728 + n * 9216;
    __nv_bfloat16* dst = g_wfrag + n * WFRAG_N;
    for (int i = threadIdx.x; i < 9216; i += 512) {
        int d = i / 96, kout = i % 96;
        int k  = d >> 4;
        int r  = d & 15;
        int half = r >> 3;
        int t2   = (r & 7) >> 1;
        int e    = r & 1;
        int nt = kout >> 3, gg = kout & 7;
        int base = (((k * 12 + nt) * 32 + gg * 4 + t2) << 3) + half * 2 + e;
        dst[base]                  = __float2bfloat16_rn(g_w1r[i]);
        dst[base + 4]              = __float2bfloat16_rn(g_w1i[i]);
        dst[WFRAG_HALF + base]     = __float2bfloat16_rn(g_w2r[i]);
        dst[WFRAG_HALF + base + 4] = __float2bfloat16_rn(g_w2i[i]);
    }
}

// -------- transpose x: [b,s,c] fp32 -> xTb [b,c,s] bf16 (paired stores) -----
__global__ void __launch_bounds__(256) transpose_x_kernel(const float* __restrict__ x) {
    __shared__ float t[64][33];
    int b  = blockIdx.z;
    int c0 = blockIdx.x * 32;
    int s0 = blockIdx.y * 64;
    int tx = threadIdx.x, ty = threadIdx.y;
    #pragma unroll
    for (int i = 0; i < 8; i++) {
        int s = s0 + ty + 8 * i;
        t[ty + 8 * i][tx] = x[((size_t)b * SEQ + s) * CH + c0 + tx];
    }
    __syncthreads();
    #pragma unroll
    for (int i = 0; i < 4; i++) {
        int cc = c0 + ty + 8 * i;
        __nv_bfloat162 v = __floats2bfloat162_rn(t[2 * tx][cc - c0], t[2 * tx + 1][cc - c0]);
        *(__nv_bfloat162*)(g_xTb + ((size_t)b * CH + cc) * SEQ + s0 + 2 * tx) = v;
    }
}

// ---------------- complex helpers ----------------
__device__ __forceinline__ float2 cadd(float2 a, float2 b) { return make_float2(a.x + b.x, a.y + b.y); }
__device__ __forceinline__ float2 csub(float2 a, float2 b) { return make_float2(a.x - b.x, a.y - b.y); }
__device__ __forceinline__ float2 cmul(float2 a, float2 b) {
    return make_float2(fmaf(a.x, b.x, -a.y * b.y), fmaf(a.x, b.y, a.y * b.x));
}

// forward DFT4 (e^{-i}), in place
__device__ __forceinline__ void dft4(float2& a0, float2& a1, float2& a2, float2& a3) {
    float2 t0 = cadd(a0, a2), t1 = csub(a0, a2);
    float2 t2 = cadd(a1, a3), t3 = csub(a1, a3);
    a0 = cadd(t0, t2);
    a2 = csub(t0, t2);
    a1 = make_float2(t1.x + t3.y, t1.y - t3.x);
    a3 = make_float2(t1.x - t3.y, t1.y + t3.x);
}

// 16-pt DFT in registers; output X[j] lands in v[4*(j&3) + (j>>2)]
__device__ __forceinline__ void dft16(float2 v[16]) {
    #pragma unroll
    for (int i = 0; i < 4; i++) dft4(v[i], v[i + 4], v[i + 8], v[i + 12]);
    const float C1 = 0.92387953251128674f, S1 = 0.38268343236508978f, R = 0.70710678118654752f;
    v[5]  = cmul(make_float2( C1, -S1), v[5]);
    v[6]  = cmul(make_float2(  R,  -R), v[6]);
    v[7]  = cmul(make_float2( S1, -C1), v[7]);
    v[9]  = cmul(make_float2(  R,  -R), v[9]);
    v[10] = make_float2(v[10].y, -v[10].x);
    v[11] = cmul(make_float2( -R,  -R), v[11]);
    v[13] = cmul(make_float2( S1, -C1), v[13]);
    v[14] = cmul(make_float2( -R,  -R), v[14]);
    v[15] = cmul(make_float2(-C1,  S1), v[15]);
    #pragma unroll
    for (int k1 = 0; k1 < 4; k1++) dft4(v[4 * k1], v[4 * k1 + 1], v[4 * k1 + 2], v[4 * k1 + 3]);
}

// Stages 1 and 2 of the 4096-pt radix-16 Stockham, operating on smem A.
// Caller must have stored stage-0 results (with twiddles) into A and synced.
// Stage 2 has p==0 for all 256 threads: twiddle-free, per-thread disjoint.
__device__ __forceinline__ void fft4096_tail(float2* A) {
    int tid = threadIdx.x;
    float2 v[16];
    // ---- stage 1: ls=4, m=16 ----
    {
        int q = tid & 15, p = tid >> 4;
        #pragma unroll
        for (int j = 0; j < 16; j++)
            v[j] = A[IX(q + ((p + (j << 4)) << 4))];
        __syncthreads();
        dft16(v);
        int twb = p << 4;
        #pragma unroll
        for (int j = 0; j < 16; j++) {
            float2 y = v[4 * (j & 3) + (j >> 2)];
            if (j > 0) y = cmul(g_wfft[j * twb], y);
            A[IX(q + ((16 * p + j) << 4))] = y;
        }
        __syncthreads();
    }
    // ---- stage 2: ls=8, p=0 -> twiddles unity, per-thread disjoint slots ----
    {
        #pragma unroll
        for (int j = 0; j < 16; j++)
            v[j] = A[IX(tid + (j << 8))];
        dft16(v);
        #pragma unroll
        for (int j = 0; j < 16; j++)
            A[IX(tid + (j << 8))] = v[4 * (j & 3) + (j >> 2)];
        __syncthreads();
    }
}

// ---------------- forward rfft: xTb[b,c,s] bf16 -> X planar bf16x2 ----------
// Stage 0 fused with the global load: thread tid's butterfly inputs are
// exactly {tid + 256j} -> load straight to registers, butterfly, store once.
__global__ void __launch_bounds__(256, 4) fwd_fft_kernel() {
    extern __shared__ char smraw[];
    float2* A = (float2*)smraw;
    int row = blockIdx.x;
    int tid = threadIdx.x;
    const __nv_bfloat162* xr = (const __nv_bfloat162*)(g_xTb + (size_t)row * SEQ);

    float2 v[16];
    #pragma unroll
    for (int j = 0; j < 16; j++) {
        __nv_bfloat162 p = xr[tid + (j << 8)];
        v[j] = make_float2(__bfloat162float(p.x), __bfloat162float(p.y));
    }
    dft16(v);
    #pragma unroll
    for (int j = 0; j < 16; j++) {
        float2 y = v[4 * (j & 3) + (j >> 2)];
        if (j > 0) y = cmul(g_wfft[j * tid], y);
        A[IX(16 * tid + j)] = y;
    }
    __syncthreads();
    fft4096_tail(A);

    __nv_bfloat162* X = g_X + (size_t)row * MODES;
    for (int k = tid; k <= 4096; k += 256) {
        float2 Zk = A[IX(k & 4095)];
        float2 Zc = A[IX((4096 - k) & 4095)];
        float Ex = 0.5f * (Zk.x + Zc.x), Ey = 0.5f * (Zk.y - Zc.y);
        float Ox = 0.5f * (Zk.x - Zc.x), Oy = 0.5f * (Zk.y + Zc.y);
        float2 w = g_wr[k];
        float re = Ex + w.x * Oy - w.y * Ox;
        float im = Ey - w.x * Ox - w.y * Oy;
        X[k] = __floats2bfloat162_rn(FWD_SCALE * re, FWD_SCALE * im);
    }
}

// ============== tensor-core block-diagonal complex 2-layer MLP ==============
#define MT    256
#define MLP_THREADS 512
#define XPAD  104
#define RS    52                             // XPAD/2 words
#define SW_OFF   0                           // 73728 B fragments
#define SXR_OFF  (2 * WFRAG_HALF * 2)        // 73728 B
#define SXI_OFF  (SXR_OFF + MT * XPAD * 2)   // +53248
#define SB_OFF   (SXI_OFF + MT * XPAD * 2)   // +53248
#define MLP_SMEM (SB_OFF + 4 * 96 * 4)       // +1536 = 181760 B

__device__ __forceinline__ void mma_bf16(float* c, const uint32_t* a, uint32_t b0, uint32_t b1) {
    asm volatile(
        "mma.sync.aligned.m16n8k16.row.col.f32.bf16.bf16.f32 "
        "{%0,%1,%2,%3}, {%4,%5,%6,%7}, {%8,%9}, {%0,%1,%2,%3};"
        : "+f"(c[0]), "+f"(c[1]), "+f"(c[2]), "+f"(c[3])
        : "r"(a[0]), "r"(a[1]), "r"(a[2]), "r"(a[3]), "r"(b0), "r"(b1));
}

__global__ void __launch_bounds__(MLP_THREADS) mlp_mma_kernel(const float* __restrict__ b1,
                                                              const float* __restrict__ b2) {
    extern __shared__ char sm[];
    __nv_bfloat16* s_wf = (__nv_bfloat16*)(sm + SW_OFF);
    __nv_bfloat16* s_xr = (__nv_bfloat16*)(sm + SXR_OFF);
    __nv_bfloat16* s_xi = (__nv_bfloat16*)(sm + SXI_OFF);
    float*         s_bv = (float*)(sm + SB_OFF);

    const int tid = threadIdx.x;
    const int n   = blockIdx.y;
    const int b   = blockIdx.z;
    const int m0  = blockIdx.x * MT;

    {
        const uint4* src = (const uint4*)(g_wfrag + (size_t)n * WFRAG_N);
        uint4* dst = (uint4*)s_wf;
        #pragma unroll
        for (int i = tid; i < WFRAG_N / 8; i += MLP_THREADS)
            dst[i] = src[i];
    }
    if (tid < 96) {
        s_bv[tid]       = b1[n * 96 + tid];
        s_bv[96 + tid]  = b1[768 + n * 96 + tid];
        s_bv[192 + tid] = b2[n * 96 + tid];
        s_bv[288 + tid] = b2[768 + n * 96 + tid];
    }

    size_t rowbase = ((size_t)b * CH + n * 96) * (size_t)MODES;
    for (int i = tid; i < 96 * MT; i += MLP_THREADS) {
        int d = i >> 8, mm = i & (MT - 1);
        int mode = m0 + mm;
        __nv_bfloat162 xv = (mode < MODES) ? g_X[rowbase + (size_t)d * MODES + mode]
                                           : __nv_bfloat162{__float2bfloat16_rn(0.f), __float2bfloat16_rn(0.f)};
        s_xr[mm * XPAD + d] = xv.x;
        s_xi[mm * XPAD + d] = xv.y;
    }
    __syncthreads();

    const int lane = tid & 31;
    const int warp = tid >> 5;
    const int g  = lane >> 2;
    const int t  = lane & 3;
    const int mrow = warp * 16;

    const uint4*    Wf = (const uint4*)s_wf;
    const uint32_t* Xr = (const uint32_t*)s_xr;
    const uint32_t* Xi = (const uint32_t*)s_xi;
    const uint32_t SGN = 0x80008000u;

    float cr[12][4], ci[12][4];

    // ---------- layer 1 ----------
    #pragma unroll
    for (int nt = 0; nt < 12; nt++) {
        float br0 = s_bv[nt * 8 + 2 * t], br1 = s_bv[nt * 8 + 2 * t + 1];
        float bi0 = s_bv[96 + nt * 8 + 2 * t], bi1 = s_bv[96 + nt * 8 + 2 * t + 1];
        cr[nt][0] = br0; cr[nt][1] = br1; cr[nt][2] = br0; cr[nt][3] = br1;
        ci[nt][0] = bi0; ci[nt][1] = bi1; ci[nt][2] = bi0; ci[nt][3] = bi1;
    }
    #pragma unroll
    for (int k = 0; k < 6; k++) {
        int kw = k * 8 + t;
        uint32_t ar[4], ai[4], nai[4];
        ar[0] = Xr[(mrow + g) * RS + kw];     ar[1] = Xr[(mrow + g + 8) * RS + kw];
        ar[2] = Xr[(mrow + g) * RS + kw + 4]; ar[3] = Xr[(mrow + g + 8) * RS + kw + 4];
        ai[0] = Xi[(mrow + g) * RS + kw];     ai[1] = Xi[(mrow + g + 8) * RS + kw];
        ai[2] = Xi[(mrow + g) * RS + kw + 4]; ai[3] = Xi[(mrow + g + 8) * RS + kw + 4];
        #pragma unroll
        for (int j = 0; j < 4; j++) nai[j] = ai[j] ^ SGN;
        #pragma unroll
        for (int nt = 0; nt < 12; nt++) {
            uint4 wv = Wf[(k * 12 + nt) * 32 + lane];
            mma_bf16(cr[nt], ar,  wv.x, wv.y);
            mma_bf16(cr[nt], nai, wv.z, wv.w);
            mma_bf16(ci[nt], ai,  wv.x, wv.y);
            mma_bf16(ci[nt], ar,  wv.z, wv.w);
        }
    }
    __syncwarp();
    {
        uint32_t* Xrw = (uint32_t*)s_xr;
        uint32_t* Xiw = (uint32_t*)s_xi;
        #pragma unroll
        for (int nt = 0; nt < 12; nt++) {
            int cw = nt * 4 + t;
            __nv_bfloat162 hh;
            hh = __floats2bfloat162_rn(fmaxf(cr[nt][0], 0.0f), fmaxf(cr[nt][1], 0.0f));
            Xrw[(mrow + g) * RS + cw] = *(uint32_t*)&hh;
            hh = __floats2bfloat162_rn(fmaxf(cr[nt][2], 0.0f), fmaxf(cr[nt][3], 0.0f));
            Xrw[(mrow + g + 8) * RS + cw] = *(uint32_t*)&hh;
            hh = __floats2bfloat162_rn(fmaxf(ci[nt][0], 0.0f), fmaxf(ci[nt][1], 0.0f));
            Xiw[(mrow + g) * RS + cw] = *(uint32_t*)&hh;
            hh = __floats2bfloat162_rn(fmaxf(ci[nt][2], 0.0f), fmaxf(ci[nt][3], 0.0f));
            Xiw[(mrow + g + 8) * RS + cw] = *(uint32_t*)&hh;
        }
    }
    __syncwarp();

    // ---------- layer 2 ----------
    #pragma unroll
    for (int nt = 0; nt < 12; nt++) {
        float br0 = s_bv[192 + nt * 8 + 2 * t], br1 = s_bv[192 + nt * 8 + 2 * t + 1];
        float bi0 = s_bv[288 + nt * 8 + 2 * t], bi1 = s_bv[288 + nt * 8 + 2 * t + 1];
        cr[nt][0] = br0; cr[nt][1] = br1; cr[nt][2] = br0; cr[nt][3] = br1;
        ci[nt][0] = bi0; ci[nt][1] = bi1; ci[nt][2] = bi0; ci[nt][3] = bi1;
    }
    #pragma unroll
    for (int k = 0; k < 6; k++) {
        int kw = k * 8 + t;
        uint32_t ar[4], ai[4], nai[4];
        ar[0] = Xr[(mrow + g) * RS + kw];     ar[1] = Xr[(mrow + g + 8) * RS + kw];
        ar[2] = Xr[(mrow + g) * RS + kw + 4]; ar[3] = Xr[(mrow + g + 8) * RS + kw + 4];
        ai[0] = Xi[(mrow + g) * RS + kw];     ai[1] = Xi[(mrow + g + 8) * RS + kw];
        ai[2] = Xi[(mrow + g) * RS + kw + 4]; ai[3] = Xi[(mrow + g + 8) * RS + kw + 4];
        #pragma unroll
        for (int j = 0; j < 4; j++) nai[j] = ai[j] ^ SGN;
        #pragma unroll
        for (int nt = 0; nt < 12; nt++) {
            uint4 wv = Wf[(72 + k * 12 + nt) * 32 + lane];
            mma_bf16(cr[nt], ar,  wv.x, wv.y);
            mma_bf16(cr[nt], nai, wv.z, wv.w);
            mma_bf16(ci[nt], ai,  wv.x, wv.y);
            mma_bf16(ci[nt], ar,  wv.z, wv.w);
        }
    }

    // ---------- softshrink + store (bf16x2) ----------
    int mode_lo = m0 + mrow + g;
    int mode_hi = mode_lo + 8;
    #pragma unroll
    for (int nt = 0; nt < 12; nt++) {
        #pragma unroll
        for (int j = 0; j < 4; j++) {
            int col  = nt * 8 + 2 * t + (j & 1);
            int mode = (j < 2) ? mode_lo : mode_hi;
            if (mode < MODES) {
                size_t off = rowbase + (size_t)col * MODES + mode;
                float vr = cr[nt][j];
                float vi = ci[nt][j];
                vr = copysignf(fmaxf(fabsf(vr) - LAM, 0.0f), vr);
                vi = copysignf(fmaxf(fabsf(vi) - LAM, 0.0f), vi);
                g_X[off] = __floats2bfloat162_rn(vr, vi);
            }
        }
    }
}

// ---------------- inverse rfft: X planar bf16x2 -> yT bf16 [b*CH+c][s] ------
// Hermitian-prep fused with stage 0 in registers.
__global__ void __launch_bounds__(256, 4) inv_fft_kernel() {
    extern __shared__ char smraw[];
    float2* A = (float2*)smraw;
    int row = blockIdx.x;
    int tid = threadIdx.x;
    const __nv_bfloat162* X = g_X + (size_t)row * MODES;

    float2 v[16];
    #pragma unroll
    for (int j = 0; j < 16; j++) {
        int k = tid + (j << 8);
        __nv_bfloat162 xk = X[k];
        __nv_bfloat162 xc = X[4096 - k];
        float xkr = __bfloat162float(xk.x), xki = __bfloat162float(xk.y);
        float xcr = __bfloat162float(xc.x), xci = __bfloat162float(xc.y);
        if (k == 0) { xki = 0.0f; xci = 0.0f; }
        float Ex = 0.5f * (xkr + xcr), Ey = 0.5f * (xki - xci);
        float Gx = 0.5f * (xkr - xcr), Gy = 0.5f * (xki + xci);
        float2 w = g_wr[k];
        float WOx = w.x * Gx - w.y * Gy;
        float WOy = w.x * Gy + w.y * Gx;
        v[j] = make_float2(INV_SCALE * (Ex - WOy), -INV_SCALE * (Ey + WOx));
    }
    dft16(v);
    #pragma unroll
    for (int j = 0; j < 16; j++) {
        float2 y = v[4 * (j & 3) + (j >> 2)];
        if (j > 0) y = cmul(g_wfft[j * tid], y);
        A[IX(16 * tid + j)] = y;
    }
    __syncthreads();
    fft4096_tail(A);

    __nv_bfloat162* out = (__nv_bfloat162*)(g_yT + (size_t)row * SEQ);
    for (int j = tid; j < 4096; j += 256) {
        float2 r = A[IX(j)];
        out[j] = __floats2bfloat162_rn(r.x, -r.y);
    }
}

// ---------------- transpose + bias: out[b,s,c] = x[b,s,c] + yT[b,c,s] -------
__global__ void __launch_bounds__(256) final_kernel(const float* __restrict__ x,
                                                    float* __restrict__ out) {
    __shared__ float t[32][33];
    int b  = blockIdx.z;
    int c0 = blockIdx.x * 32;
    int s0 = blockIdx.y * 32;
    int tx = threadIdx.x, ty = threadIdx.y;
    #pragma unroll
    for (int i = 0; i < 4; i++) {
        int cc = c0 + ty + 8 * i;
        t[ty + 8 * i][tx] = __bfloat162float(g_yT[((size_t)b * CH + cc) * SEQ + s0 + tx]);
    }
    __syncthreads();
    #pragma unroll
    for (int i = 0; i < 4; i++) {
        int s = s0 + ty + 8 * i;
        size_t off = ((size_t)b * SEQ + s) * CH + c0 + tx;
        out[off] = x[off] + t[tx][ty + 8 * i];
    }
}

// ---------------- launcher ----------------
extern "C" void kernel_launch(void* const* d_in, const int* in_sizes, int n_in,
                              void* d_out, int out_size) {
    const float* x  = (const float*)d_in[0];
    const float* w1 = (const float*)d_in[1];
    const float* b1 = (const float*)d_in[2];
    const float* w2 = (const float*)d_in[3];
    const float* b2 = (const float*)d_in[4];
    float* out = (float*)d_out;

    cudaFuncSetAttribute(fwd_fft_kernel, cudaFuncAttributeMaxDynamicSharedMemorySize, FFT_SMEM);
    cudaFuncSetAttribute(inv_fft_kernel, cudaFuncAttributeMaxDynamicSharedMemorySize, FFT_SMEM);
    cudaFuncSetAttribute(mlp_mma_kernel, cudaFuncAttributeMaxDynamicSharedMemorySize, MLP_SMEM);

    init_tables_kernel<<<17, 256>>>();
    pack_w_kernel<<<NBLK, 512>>>(w1, w2);
    transpose_x_kernel<<<dim3(CH / 32, SEQ / 64, BATCH), dim3(32, 8)>>>(x);
    fwd_fft_kernel<<<BATCH * CH, 256, FFT_SMEM>>>();
    mlp_mma_kernel<<<dim3((MODES + MT - 1) / MT, NBLK, BATCH), MLP_THREADS, MLP_SMEM>>>(b1, b2);
    inv_fft_kernel<<<BATCH * CH, 256, FFT_SMEM>>>();
    final_kernel<<<dim3(CH / 32, SEQ / 32, BATCH), dim3(32, 8)>>>(x, out);
}